// round 1
// baseline (speedup 1.0000x reference)
#include <cuda_runtime.h>
#include <math.h>

#define Bn 64
#define Sn 2048
#define Un 1024
#define Vn 50257
#define Ln 8

// ---------------- scratch (device globals; no allocs allowed) ----------------
__device__ float g_q2[Bn * Un];            // query_h@W2 + b2 + b1
__device__ float g_score[Bn * Sn];
__device__ float g_attnw[Bn * Sn];
__device__ float g_ctx[Bn * Un];
__device__ float g_x[Bn * Un];             // running LSTM input x (updated in place)
__device__ float g_zpart[4 * Bn * 4096];   // k-split partials for lstm gemm
__device__ float g_logits[(size_t)Bn * Vn];

// ---------------- init x = dec_input[:,0,:] ----------------
__global__ void copy_x_kernel(const float* __restrict__ dec) {
    int i = blockIdx.x * 256 + threadIdx.x;
    g_x[i] = dec[i];
}

// ---------------- q2[b,v] = query_h[b]@W2[:,v] + b2[v] + b1[v] ----------------
__global__ void q2_kernel(const float* __restrict__ qh, const float* __restrict__ W2,
                          const float* __restrict__ b1, const float* __restrict__ b2) {
    int b = blockIdx.x;
    int v = blockIdx.y * 128 + threadIdx.x;
    const float* q = qh + b * Un;
    float a0 = 0.f, a1 = 0.f, a2 = 0.f, a3 = 0.f;
    #pragma unroll 1
    for (int k = 0; k < Un; k += 4) {
        a0 += q[k + 0] * W2[(size_t)(k + 0) * Un + v];
        a1 += q[k + 1] * W2[(size_t)(k + 1) * Un + v];
        a2 += q[k + 2] * W2[(size_t)(k + 2) * Un + v];
        a3 += q[k + 3] * W2[(size_t)(k + 3) * Un + v];
    }
    g_q2[b * Un + v] = (a0 + a1) + (a2 + a3) + b1[v] + b2[v];
}

// ---------------- fused score GEMM ----------------
// score[b,s] = sum_v tanh( enc[b,s,:]@W1[:,v] + q2[b,v] ) * attnV[v] + bV
// Block: 128 rows of S (one b), loops over 16 N-tiles of 64 cols, K=1024.
__global__ __launch_bounds__(256) void score_kernel(
    const float* __restrict__ enc, const float* __restrict__ W1,
    const float* __restrict__ attnV, const float* __restrict__ attnbV) {
    __shared__ float As[16][128];  // [k][s]
    __shared__ float Bs[16][64];   // [k][n]
    const int b = blockIdx.y;
    const int s0 = blockIdx.x * 128;
    const int tid = threadIdx.x;
    const int tx = tid & 15;       // 16 col groups of 4
    const int ty = tid >> 4;       // 16 row groups of 8
    const float* encB = enc + ((size_t)b * Sn + s0) * Un;

    float sc[8];
    #pragma unroll
    for (int i = 0; i < 8; i++) sc[i] = 0.f;

    for (int nt = 0; nt < Un / 64; nt++) {
        float acc[8][4];
        #pragma unroll
        for (int i = 0; i < 8; i++)
            #pragma unroll
            for (int j = 0; j < 4; j++) acc[i][j] = 0.f;

        for (int k0 = 0; k0 < Un; k0 += 16) {
            // As: 128x16 -> transposed, 512 float4, 2 per thread
            #pragma unroll
            for (int l = 0; l < 2; l++) {
                int idx = tid + l * 256;
                int r = idx >> 2;
                int c4 = (idx & 3) << 2;
                float4 v = *(const float4*)(encB + (size_t)r * Un + k0 + c4);
                As[c4 + 0][r] = v.x; As[c4 + 1][r] = v.y;
                As[c4 + 2][r] = v.z; As[c4 + 3][r] = v.w;
            }
            // Bs: 16x64, 256 float4, 1 per thread
            {
                int c  = tid >> 4;
                int n4 = (tid & 15) << 2;
                float4 v = *(const float4*)(W1 + (size_t)(k0 + c) * Un + nt * 64 + n4);
                Bs[c][n4 + 0] = v.x; Bs[c][n4 + 1] = v.y;
                Bs[c][n4 + 2] = v.z; Bs[c][n4 + 3] = v.w;
            }
            __syncthreads();
            #pragma unroll
            for (int k = 0; k < 16; k++) {
                float a[8], bb[4];
                #pragma unroll
                for (int i = 0; i < 8; i++) a[i] = As[k][ty * 8 + i];
                #pragma unroll
                for (int j = 0; j < 4; j++) bb[j] = Bs[k][tx * 4 + j];
                #pragma unroll
                for (int i = 0; i < 8; i++)
                    #pragma unroll
                    for (int j = 0; j < 4; j++) acc[i][j] += a[i] * bb[j];
            }
            __syncthreads();
        }
        // fused epilogue: tanh then dot with attn_V
        #pragma unroll
        for (int j = 0; j < 4; j++) {
            int v = nt * 64 + tx * 4 + j;
            float qv = g_q2[b * Un + v];
            float av = attnV[v];
            #pragma unroll
            for (int i = 0; i < 8; i++)
                sc[i] += tanhf(acc[i][j] + qv) * av;
        }
    }
    // reduce across the 16 tx lanes (stay within 16-lane halves of the warp)
    #pragma unroll
    for (int off = 8; off >= 1; off >>= 1)
        #pragma unroll
        for (int i = 0; i < 8; i++)
            sc[i] += __shfl_xor_sync(0xffffffffu, sc[i], off);
    if (tx == 0) {
        float bV = attnbV[0];
        #pragma unroll
        for (int i = 0; i < 8; i++)
            g_score[b * Sn + s0 + ty * 8 + i] = sc[i] + bV;
    }
}

// ---------------- softmax over S ----------------
__global__ void softmax_s_kernel(float* __restrict__ out_attnw) {
    int b = blockIdx.x;
    int tid = threadIdx.x;
    __shared__ float red[256];
    float m = -1e30f;
    for (int s = tid; s < Sn; s += 256) m = fmaxf(m, g_score[b * Sn + s]);
    red[tid] = m; __syncthreads();
    for (int o = 128; o > 0; o >>= 1) { if (tid < o) red[tid] = fmaxf(red[tid], red[tid + o]); __syncthreads(); }
    m = red[0]; __syncthreads();
    float sum = 0.f;
    for (int s = tid; s < Sn; s += 256) {
        float e = expf(g_score[b * Sn + s] - m);
        g_attnw[b * Sn + s] = e;
        sum += e;
    }
    red[tid] = sum; __syncthreads();
    for (int o = 128; o > 0; o >>= 1) { if (tid < o) red[tid] += red[tid + o]; __syncthreads(); }
    float inv = 1.f / red[0];
    for (int s = tid; s < Sn; s += 256) {
        float w = g_attnw[b * Sn + s] * inv;
        g_attnw[b * Sn + s] = w;
        out_attnw[b * Sn + s] = w;
    }
}

// ---------------- ctx[b,u] = sum_s attn_w[b,s]*enc[b,s,u] ----------------
__global__ void ctx_kernel(const float* __restrict__ enc) {
    int b = blockIdx.x;
    int u = blockIdx.y * 128 + threadIdx.x;
    const float* e = enc + (size_t)b * Sn * Un + u;
    const float* w = g_attnw + b * Sn;
    float a0 = 0.f, a1 = 0.f, a2 = 0.f, a3 = 0.f;
    for (int s = 0; s < Sn; s += 4) {
        a0 += w[s + 0] * e[(size_t)(s + 0) * Un];
        a1 += w[s + 1] * e[(size_t)(s + 1) * Un];
        a2 += w[s + 2] * e[(size_t)(s + 2) * Un];
        a3 += w[s + 3] * e[(size_t)(s + 3) * Un];
    }
    g_ctx[b * Un + u] = (a0 + a1) + (a2 + a3);
}

// ---------------- LSTM GEMM: z = [x|ctx](64x2048) @ W(2048x4096), k-split=4 ----------------
__global__ __launch_bounds__(128) void lstm_gemm_kernel(const float* __restrict__ Wl) {
    __shared__ float As[16][64];   // [k][m]
    __shared__ float Bs[16][64];   // [k][n]
    const int nt = blockIdx.x;     // 64 tiles of 64 cols
    const int ks = blockIdx.y;     // 4 k-splits of 512
    const int tid = threadIdx.x;
    const int tx = tid & 15;
    const int ty = tid >> 4;       // 0..7, 8 rows each
    float acc[8][4];
    #pragma unroll
    for (int i = 0; i < 8; i++)
        #pragma unroll
        for (int j = 0; j < 4; j++) acc[i][j] = 0.f;

    const int kb = ks * 512;
    for (int k0 = kb; k0 < kb + 512; k0 += 16) {
        #pragma unroll
        for (int l = 0; l < 2; l++) {
            int idx = tid + l * 128;
            int m = idx >> 2;
            int c4 = (idx & 3) << 2;
            int kg = k0 + c4;
            const float* src = (kg < Un) ? (g_x + m * Un + kg)
                                         : (g_ctx + m * Un + (kg - Un));
            float4 v = *(const float4*)src;
            As[c4 + 0][m] = v.x; As[c4 + 1][m] = v.y;
            As[c4 + 2][m] = v.z; As[c4 + 3][m] = v.w;
        }
        #pragma unroll
        for (int l = 0; l < 2; l++) {
            int idx = tid + l * 128;
            int c = idx >> 4;
            int n4 = (idx & 15) << 2;
            float4 v = *(const float4*)(Wl + (size_t)(k0 + c) * 4096 + nt * 64 + n4);
            Bs[c][n4 + 0] = v.x; Bs[c][n4 + 1] = v.y;
            Bs[c][n4 + 2] = v.z; Bs[c][n4 + 3] = v.w;
        }
        __syncthreads();
        #pragma unroll
        for (int k = 0; k < 16; k++) {
            float a[8], bb[4];
            #pragma unroll
            for (int i = 0; i < 8; i++) a[i] = As[k][ty * 8 + i];
            #pragma unroll
            for (int j = 0; j < 4; j++) bb[j] = Bs[k][tx * 4 + j];
            #pragma unroll
            for (int i = 0; i < 8; i++)
                #pragma unroll
                for (int j = 0; j < 4; j++) acc[i][j] += a[i] * bb[j];
        }
        __syncthreads();
    }
    #pragma unroll
    for (int i = 0; i < 8; i++)
        #pragma unroll
        for (int j = 0; j < 4; j++) {
            int m = ty * 8 + i;
            int n = nt * 64 + tx * 4 + j;
            g_zpart[((ks * Bn) + m) * 4096 + n] = acc[i][j];
        }
}

// ---------------- LSTM activation: gates -> c,h; x updated in place ----------------
__global__ void lstm_act_kernel(const float* __restrict__ lb,
                                float* __restrict__ hs, float* __restrict__ cs,
                                int layer, int residual) {
    int b = blockIdx.x;
    int u = threadIdx.x;  // 1024
    float zi = lb[u], zg = lb[u + 2048], zo = lb[u + 3072];
    #pragma unroll
    for (int ks = 0; ks < 4; ks++) {
        const float* zp = g_zpart + ((size_t)(ks * Bn) + b) * 4096;
        zi += zp[u];
        zg += zp[u + 2048];
        zo += zp[u + 3072];
    }
    float c = (1.f / (1.f + expf(-zi))) * tanhf(zg);
    float h = (1.f / (1.f + expf(-zo))) * tanhf(c);
    size_t o = ((size_t)layer * Bn + b) * Un + u;
    hs[o] = h;
    cs[o] = c;
    float xo = g_x[b * Un + u];
    g_x[b * Un + u] = residual ? (h + xo) : h;
}

// ---------------- dense GEMM: logits = x(64x1024)@W(1024x50257)+b ----------------
__global__ __launch_bounds__(128) void dense_gemm_kernel(const float* __restrict__ W,
                                                         const float* __restrict__ db) {
    __shared__ float As[16][64];
    __shared__ float Bs[16][64];
    const int n0 = blockIdx.x * 64;
    const int tid = threadIdx.x;
    const int tx = tid & 15;
    const int ty = tid >> 4;
    float acc[8][4];
    #pragma unroll
    for (int i = 0; i < 8; i++)
        #pragma unroll
        for (int j = 0; j < 4; j++) acc[i][j] = 0.f;

    for (int k0 = 0; k0 < Un; k0 += 16) {
        #pragma unroll
        for (int l = 0; l < 2; l++) {
            int idx = tid + l * 128;
            int m = idx >> 2;
            int c4 = (idx & 3) << 2;
            float4 v = *(const float4*)(g_x + m * Un + k0 + c4);
            As[c4 + 0][m] = v.x; As[c4 + 1][m] = v.y;
            As[c4 + 2][m] = v.z; As[c4 + 3][m] = v.w;
        }
        // W row stride (50257) is odd -> scalar, guarded loads
        #pragma unroll
        for (int l = 0; l < 8; l++) {
            int idx = tid + l * 128;
            int c = idx >> 6;
            int n = idx & 63;
            int ng = n0 + n;
            Bs[c][n] = (ng < Vn) ? W[(size_t)(k0 + c) * Vn + ng] : 0.f;
        }
        __syncthreads();
        #pragma unroll
        for (int k = 0; k < 16; k++) {
            float a[8], bb[4];
            #pragma unroll
            for (int i = 0; i < 8; i++) a[i] = As[k][ty * 8 + i];
            #pragma unroll
            for (int j = 0; j < 4; j++) bb[j] = Bs[k][tx * 4 + j];
            #pragma unroll
            for (int i = 0; i < 8; i++)
                #pragma unroll
                for (int j = 0; j < 4; j++) acc[i][j] += a[i] * bb[j];
        }
        __syncthreads();
    }
    #pragma unroll
    for (int i = 0; i < 8; i++)
        #pragma unroll
        for (int j = 0; j < 4; j++) {
            int m = ty * 8 + i;
            int n = n0 + tx * 4 + j;
            if (n < Vn) g_logits[(size_t)m * Vn + n] = acc[i][j] + db[n];
        }
}

// ---------------- softmax over V -> probs ----------------
__global__ void softmax_v_kernel(float* __restrict__ probs) {
    int b = blockIdx.x;
    int tid = threadIdx.x;  // 1024
    __shared__ float red[1024];
    const float* lg = g_logits + (size_t)b * Vn;
    float m = -1e30f;
    for (int j = tid; j < Vn; j += 1024) m = fmaxf(m, lg[j]);
    red[tid] = m; __syncthreads();
    for (int o = 512; o > 0; o >>= 1) { if (tid < o) red[tid] = fmaxf(red[tid], red[tid + o]); __syncthreads(); }
    m = red[0]; __syncthreads();
    float sum = 0.f;
    float* pb = probs + (size_t)b * Vn;
    for (int j = tid; j < Vn; j += 1024) {
        float e = expf(lg[j] - m);
        pb[j] = e;
        sum += e;
    }
    red[tid] = sum; __syncthreads();
    for (int o = 512; o > 0; o >>= 1) { if (tid < o) red[tid] += red[tid + o]; __syncthreads(); }
    float inv = 1.f / red[0];
    for (int j = tid; j < Vn; j += 1024) pb[j] *= inv;
}

// ---------------- launch ----------------
extern "C" void kernel_launch(void* const* d_in, const int* in_sizes, int n_in,
                              void* d_out, int out_size) {
    const float* enc = (const float*)d_in[0];
    const float* dec = (const float*)d_in[1];
    const float* qh  = (const float*)d_in[2];
    const float* W1  = (const float*)d_in[3];
    const float* b1  = (const float*)d_in[4];
    const float* W2  = (const float*)d_in[5];
    const float* b2  = (const float*)d_in[6];
    const float* aV  = (const float*)d_in[7];
    const float* abV = (const float*)d_in[8];
    const float* lW  = (const float*)d_in[9];
    const float* lb  = (const float*)d_in[10];
    const float* dW  = (const float*)d_in[11];
    const float* db  = (const float*)d_in[12];

    float* out   = (float*)d_out;
    float* probs = out;                                  // (B,1,V)
    float* hs    = out + (size_t)Bn * Vn;                // (L,B,U)
    float* cs    = hs + (size_t)Ln * Bn * Un;            // (L,B,U)
    float* attnw = cs + (size_t)Ln * Bn * Un;            // (B,S,1)

    static const int RES[8] = {0, 0, 1, 1, 1, 1, 1, 0};

    copy_x_kernel<<<256, 256>>>(dec);
    q2_kernel<<<dim3(Bn, 8), 128>>>(qh, W2, b1, b2);
    score_kernel<<<dim3(Sn / 128, Bn), 256>>>(enc, W1, aV, abV);
    softmax_s_kernel<<<Bn, 256>>>(attnw);
    ctx_kernel<<<dim3(Bn, 8), 128>>>(enc);

    for (int l = 0; l < Ln; l++) {
        lstm_gemm_kernel<<<dim3(64, 4), 128>>>(lW + (size_t)l * 2048 * 4096);
        lstm_act_kernel<<<Bn, 1024>>>(lb + (size_t)l * 4096, hs, cs, l, RES[l]);
    }

    dense_gemm_kernel<<<(Vn + 63) / 64, 128>>>(dW, db);
    softmax_v_kernel<<<Bn, 1024>>>(probs);
}

// round 3
// speedup vs baseline: 3.0098x; 3.0098x over previous
#include <cuda_runtime.h>
#include <cuda_fp16.h>
#include <math.h>
#include <stdint.h>

#define Bn 64
#define Sn 2048
#define Un 1024
#define Vn 50257
#define Ln 8

// ---------------- scratch (device globals; no allocs allowed) ----------------
__device__ float g_q2[Bn * Un];            // query_h@W2 + b2 + b1
__device__ float g_score[Bn * Sn];
__device__ float g_attnw[Bn * Sn];
__device__ float g_ctx[Bn * Un];
__device__ float g_x[Bn * Un];             // running LSTM input x
__device__ float g_zpart[4 * Bn * 4096];   // k-split partials for lstm gemm
__device__ float g_logits[(size_t)Bn * Vn];
__device__ __half g_W1h[(size_t)Un * Un];  // W1 transposed to [n][k], fp16

// ======================= helpers =======================
__device__ __forceinline__ uint32_t smem_u32(const void* p) {
    uint32_t a;
    asm("{ .reg .u64 t; cvta.to.shared.u64 t, %1; cvt.u32.u64 %0, t; }" : "=r"(a) : "l"(p));
    return a;
}
__device__ __forceinline__ float tanh_fast(float x) {
    float y;
    asm("tanh.approx.f32 %0, %1;" : "=f"(y) : "f"(x));
    return y;
}
#define LDSM4(r0, r1, r2, r3, addr) \
    asm volatile("ldmatrix.sync.aligned.m8n8.x4.shared.b16 {%0,%1,%2,%3}, [%4];" \
                 : "=r"(r0), "=r"(r1), "=r"(r2), "=r"(r3) : "r"(addr))
__device__ __forceinline__ void mma16816(float* d, const uint32_t* a, uint32_t b0, uint32_t b1) {
    asm volatile(
        "mma.sync.aligned.m16n8k16.row.col.f32.f16.f16.f32 "
        "{%0,%1,%2,%3}, {%4,%5,%6,%7}, {%8,%9}, {%0,%1,%2,%3};"
        : "+f"(d[0]), "+f"(d[1]), "+f"(d[2]), "+f"(d[3])
        : "r"(a[0]), "r"(a[1]), "r"(a[2]), "r"(a[3]), "r"(b0), "r"(b1));
}
__device__ __forceinline__ void cp16(uint32_t s, const void* g) {
    asm volatile("cp.async.ca.shared.global [%0], [%1], 16;" :: "r"(s), "l"(g));
}
#define CP_COMMIT() asm volatile("cp.async.commit_group;" ::: "memory")
#define CP_WAIT1() asm volatile("cp.async.wait_group 1;" ::: "memory")
#define CP_WAIT0() asm volatile("cp.async.wait_group 0;" ::: "memory")

// ---------------- init x = dec_input[:,0,:] ----------------
__global__ void copy_x_kernel(const float* __restrict__ dec) {
    int i = blockIdx.x * 256 + threadIdx.x;
    g_x[i] = dec[i];
}

// ---------------- convert W1[k][n] fp32 -> g_W1h[n][k] fp16 ----------------
__global__ void conv_w1_kernel(const float* __restrict__ W1) {
    __shared__ float t[32][33];
    int n0 = blockIdx.x * 32, k0 = blockIdx.y * 32;
    int x = threadIdx.x, y = threadIdx.y;  // 32 x 8
    #pragma unroll
    for (int i = 0; i < 32; i += 8)
        t[y + i][x] = W1[(size_t)(k0 + y + i) * Un + n0 + x];
    __syncthreads();
    #pragma unroll
    for (int i = 0; i < 32; i += 8)
        g_W1h[(size_t)(n0 + y + i) * Un + k0 + x] = __float2half_rn(t[x][y + i]);
}

// ---------------- q2[b,v] = query_h[b]@W2[:,v] + b2[v] + b1[v] ----------------
__global__ void q2_kernel(const float* __restrict__ qh, const float* __restrict__ W2,
                          const float* __restrict__ b1, const float* __restrict__ b2) {
    int b = blockIdx.x;
    int v = blockIdx.y * 128 + threadIdx.x;
    const float* q = qh + b * Un;
    float a0 = 0.f, a1 = 0.f, a2 = 0.f, a3 = 0.f;
    #pragma unroll 1
    for (int k = 0; k < Un; k += 4) {
        a0 += q[k + 0] * W2[(size_t)(k + 0) * Un + v];
        a1 += q[k + 1] * W2[(size_t)(k + 1) * Un + v];
        a2 += q[k + 2] * W2[(size_t)(k + 2) * Un + v];
        a3 += q[k + 3] * W2[(size_t)(k + 3) * Un + v];
    }
    g_q2[b * Un + v] = (a0 + a1) + (a2 + a3) + b1[v] + b2[v];
}

// =================== HMMA fused score GEMM ===================
// score[b,s] = sum_v tanh( enc[b,s,:]@W1[:,v] + q2[b,v] ) * attnV[v] + bV
// CTA: 64 S-rows of one b. Full A panel (64x1024 fp16, 128KB) in SMEM.
// N looped in 16 tiles of 64; B (W1h[n][k]) streamed via cp.async double buffer.
// Accumulators in registers; epilogue fuses tanh + attnV dot.
#define SCOFF_A 0           // 64*2048 = 131072
#define SCOFF_B 131072      // 2 * 8192
#define SCOFF_Q2 147456     // 4096
#define SCOFF_AV 151552     // 4096
#define SCOFF_RED 155648    // 256
#define SC_SMEM 155904

__global__ __launch_bounds__(256, 1)
void score_mma_kernel(const float* __restrict__ enc, const float* __restrict__ attnV,
                      const float* __restrict__ attnbV) {
    extern __shared__ char smem[];
    const uint32_t sb = smem_u32(smem);
    const int tid = threadIdx.x;
    const int lane = tid & 31;
    const int wid = tid >> 5;
    const int wm = wid & 3;      // m row-group: rows wm*16..+16
    const int wn = wid >> 2;     // n half: cols wn*32..+32 of each 64-tile
    const int b = blockIdx.y;
    const int s0 = blockIdx.x * 64;

    float* q2s = (float*)(smem + SCOFF_Q2);
    float* avs = (float*)(smem + SCOFF_AV);
    float* red = (float*)(smem + SCOFF_RED);

    for (int i = tid; i < Un; i += 256) {
        q2s[i] = g_q2[b * Un + i];
        avs[i] = attnV[i];
    }

    // ---- A panel: convert 64x1024 fp32 -> fp16, swizzled 16B chunks ----
    // chunk c (0..127) of row r stored at chunk (c ^ (r&7))
    const float* encB = enc + ((size_t)b * Sn + s0) * Un;
    #pragma unroll 1
    for (int it = 0; it < 32; it++) {
        int idx = it * 256 + tid;
        int r = idx >> 7;
        int c = idx & 127;
        const float4* src = (const float4*)(encB + (size_t)r * Un + c * 8);
        float4 v0 = src[0], v1 = src[1];
        __half2 h0 = __floats2half2_rn(v0.x, v0.y);
        __half2 h1 = __floats2half2_rn(v0.z, v0.w);
        __half2 h2 = __floats2half2_rn(v1.x, v1.y);
        __half2 h3 = __floats2half2_rn(v1.z, v1.w);
        uint4 u;
        u.x = *reinterpret_cast<uint32_t*>(&h0);
        u.y = *reinterpret_cast<uint32_t*>(&h1);
        u.z = *reinterpret_cast<uint32_t*>(&h2);
        u.w = *reinterpret_cast<uint32_t*>(&h3);
        int cs = c ^ (r & 7);
        *reinterpret_cast<uint4*>(smem + SCOFF_A + r * 2048 + cs * 16) = u;
    }
    __syncthreads();

    // per-lane ldmatrix A address components (row = wm*16 + (lane&15))
    const int arow = wm * 16 + (lane & 15);
    const uint32_t abase = sb + SCOFF_A + arow * 2048;
    const int axr = arow & 7;
    const int ahi = lane >> 4;

    // per-lane B address components (two 16-row quads per warp)
    const int bn0 = wn * 32 + (lane & 15);        // quad 0 n-row
    const int bn1 = bn0 + 16;                     // quad 1 n-row
    const int bhi = lane >> 4;

    const int g = lane >> 2;
    const int t = lane & 3;
    const float bV = attnbV[0];
    float p0 = 0.f, p1 = 0.f;

    // B tile loader: tile = 64n x 64k fp16 (8KB), 512 16B chunks, 2 per thread
    auto loadB = [&](int nt, int kk, int buf) {
        #pragma unroll
        for (int h = 0; h < 2; h++) {
            int ch = h * 256 + tid;
            int n = ch >> 3;
            int ck = ch & 7;
            uint32_t daddr = sb + SCOFF_B + buf * 8192 + n * 128 + ((ck ^ (n & 7)) << 4);
            cp16(daddr, g_W1h + (size_t)(nt * 64 + n) * Un + kk * 64 + ck * 8);
        }
    };

    #pragma unroll 1
    for (int nt = 0; nt < 16; nt++) {
        float d[4][4];
        #pragma unroll
        for (int j = 0; j < 4; j++)
            #pragma unroll
            for (int i = 0; i < 4; i++) d[j][i] = 0.f;

        loadB(nt, 0, 0);
        CP_COMMIT();

        #pragma unroll 1
        for (int kk = 0; kk < 16; kk++) {
            if (kk < 15) {
                loadB(nt, kk + 1, (kk + 1) & 1);
                CP_COMMIT();
                CP_WAIT1();
            } else {
                CP_WAIT0();
            }
            __syncthreads();
            const uint32_t bbuf = sb + SCOFF_B + (kk & 1) * 8192;
            #pragma unroll
            for (int kk2 = 0; kk2 < 4; kk2++) {
                const int K16 = kk * 4 + kk2;
                uint32_t a[4];
                LDSM4(a[0], a[1], a[2], a[3], abase + (((K16 * 2 + ahi) ^ axr) << 4));
                uint32_t q0[4], q1[4];
                {
                    int ck = kk2 * 2 + bhi;
                    LDSM4(q0[0], q0[1], q0[2], q0[3],
                          bbuf + bn0 * 128 + ((ck ^ (bn0 & 7)) << 4));
                    LDSM4(q1[0], q1[1], q1[2], q1[3],
                          bbuf + bn1 * 128 + ((ck ^ (bn1 & 7)) << 4));
                }
                mma16816(d[0], a, q0[0], q0[2]);
                mma16816(d[1], a, q0[1], q0[3]);
                mma16816(d[2], a, q1[0], q1[2]);
                mma16816(d[3], a, q1[1], q1[3]);
            }
            __syncthreads();
        }
        // epilogue on register fragments: tanh(D + q2) * attnV, reduce over cols
        #pragma unroll
        for (int j = 0; j < 4; j++) {
            int c0 = nt * 64 + wn * 32 + j * 8 + 2 * t;
            float qa = q2s[c0], qb = q2s[c0 + 1];
            float va = avs[c0], vb = avs[c0 + 1];
            p0 += tanh_fast(d[j][0] + qa) * va + tanh_fast(d[j][1] + qb) * vb;
            p1 += tanh_fast(d[j][2] + qa) * va + tanh_fast(d[j][3] + qb) * vb;
        }
    }
    // reduce over quad lanes (cols within fragment)
    p0 += __shfl_xor_sync(0xffffffffu, p0, 1);
    p0 += __shfl_xor_sync(0xffffffffu, p0, 2);
    p1 += __shfl_xor_sync(0xffffffffu, p1, 1);
    p1 += __shfl_xor_sync(0xffffffffu, p1, 2);
    const int row = wm * 16 + g;
    if (t == 0 && wn == 1) {
        red[row] = p0;
        red[row + 8] = p1;
    }
    __syncthreads();
    if (t == 0 && wn == 0) {
        g_score[b * Sn + s0 + row] = p0 + red[row] + bV;
        g_score[b * Sn + s0 + row + 8] = p1 + red[row + 8] + bV;
    }
}

// ---------------- softmax over S ----------------
__global__ void softmax_s_kernel(float* __restrict__ out_attnw) {
    int b = blockIdx.x;
    int tid = threadIdx.x;
    __shared__ float red[256];
    float m = -1e30f;
    for (int s = tid; s < Sn; s += 256) m = fmaxf(m, g_score[b * Sn + s]);
    red[tid] = m; __syncthreads();
    for (int o = 128; o > 0; o >>= 1) { if (tid < o) red[tid] = fmaxf(red[tid], red[tid + o]); __syncthreads(); }
    m = red[0]; __syncthreads();
    float sum = 0.f;
    for (int s = tid; s < Sn; s += 256) {
        float e = expf(g_score[b * Sn + s] - m);
        g_attnw[b * Sn + s] = e;
        sum += e;
    }
    red[tid] = sum; __syncthreads();
    for (int o = 128; o > 0; o >>= 1) { if (tid < o) red[tid] += red[tid + o]; __syncthreads(); }
    float inv = 1.f / red[0];
    for (int s = tid; s < Sn; s += 256) {
        float w = g_attnw[b * Sn + s] * inv;
        g_attnw[b * Sn + s] = w;
        out_attnw[b * Sn + s] = w;
    }
}

// ---------------- ctx[b,u] = sum_s attn_w[b,s]*enc[b,s,u] ----------------
__global__ void ctx_kernel(const float* __restrict__ enc) {
    int b = blockIdx.x;
    int u = blockIdx.y * 128 + threadIdx.x;
    const float* e = enc + (size_t)b * Sn * Un + u;
    const float* w = g_attnw + b * Sn;
    float a0 = 0.f, a1 = 0.f, a2 = 0.f, a3 = 0.f;
    for (int s = 0; s < Sn; s += 4) {
        a0 += w[s + 0] * e[(size_t)(s + 0) * Un];
        a1 += w[s + 1] * e[(size_t)(s + 1) * Un];
        a2 += w[s + 2] * e[(size_t)(s + 2) * Un];
        a3 += w[s + 3] * e[(size_t)(s + 3) * Un];
    }
    g_ctx[b * Un + u] = (a0 + a1) + (a2 + a3);
}

// ---------------- LSTM GEMM: z = [x|ctx](64x2048) @ W(2048x4096), k-split=4 ----------------
__global__ __launch_bounds__(128) void lstm_gemm_kernel(const float* __restrict__ Wl) {
    __shared__ float As[16][64];
    __shared__ float Bs[16][64];
    const int nt = blockIdx.x;
    const int ks = blockIdx.y;
    const int tid = threadIdx.x;
    const int tx = tid & 15;
    const int ty = tid >> 4;
    float acc[8][4];
    #pragma unroll
    for (int i = 0; i < 8; i++)
        #pragma unroll
        for (int j = 0; j < 4; j++) acc[i][j] = 0.f;

    const int kb = ks * 512;
    for (int k0 = kb; k0 < kb + 512; k0 += 16) {
        #pragma unroll
        for (int l = 0; l < 2; l++) {
            int idx = tid + l * 128;
            int m = idx >> 2;
            int c4 = (idx & 3) << 2;
            int kg = k0 + c4;
            const float* src = (kg < Un) ? (g_x + m * Un + kg)
                                         : (g_ctx + m * Un + (kg - Un));
            float4 v = *(const float4*)src;
            As[c4 + 0][m] = v.x; As[c4 + 1][m] = v.y;
            As[c4 + 2][m] = v.z; As[c4 + 3][m] = v.w;
        }
        #pragma unroll
        for (int l = 0; l < 2; l++) {
            int idx = tid + l * 128;
            int c = idx >> 4;
            int n4 = (idx & 15) << 2;
            float4 v = *(const float4*)(Wl + (size_t)(k0 + c) * 4096 + nt * 64 + n4);
            Bs[c][n4 + 0] = v.x; Bs[c][n4 + 1] = v.y;
            Bs[c][n4 + 2] = v.z; Bs[c][n4 + 3] = v.w;
        }
        __syncthreads();
        #pragma unroll
        for (int k = 0; k < 16; k++) {
            float a[8], bb[4];
            #pragma unroll
            for (int i = 0; i < 8; i++) a[i] = As[k][ty * 8 + i];
            #pragma unroll
            for (int j = 0; j < 4; j++) bb[j] = Bs[k][tx * 4 + j];
            #pragma unroll
            for (int i = 0; i < 8; i++)
                #pragma unroll
                for (int j = 0; j < 4; j++) acc[i][j] += a[i] * bb[j];
        }
        __syncthreads();
    }
    #pragma unroll
    for (int i = 0; i < 8; i++)
        #pragma unroll
        for (int j = 0; j < 4; j++) {
            int m = ty * 8 + i;
            int n = nt * 64 + tx * 4 + j;
            g_zpart[((ks * Bn) + m) * 4096 + n] = acc[i][j];
        }
}

// ---------------- LSTM activation ----------------
__global__ void lstm_act_kernel(const float* __restrict__ lb,
                                float* __restrict__ hs, float* __restrict__ cs,
                                int layer, int residual) {
    int b = blockIdx.x;
    int u = threadIdx.x;
    float zi = lb[u], zg = lb[u + 2048], zo = lb[u + 3072];
    #pragma unroll
    for (int ks = 0; ks < 4; ks++) {
        const float* zp = g_zpart + ((size_t)(ks * Bn) + b) * 4096;
        zi += zp[u];
        zg += zp[u + 2048];
        zo += zp[u + 3072];
    }
    float c = (1.f / (1.f + expf(-zi))) * tanhf(zg);
    float h = (1.f / (1.f + expf(-zo))) * tanhf(c);
    size_t o = ((size_t)layer * Bn + b) * Un + u;
    hs[o] = h;
    cs[o] = c;
    float xo = g_x[b * Un + u];
    g_x[b * Un + u] = residual ? (h + xo) : h;
}

// ---------------- dense GEMM ----------------
__global__ __launch_bounds__(128) void dense_gemm_kernel(const float* __restrict__ W,
                                                         const float* __restrict__ db) {
    __shared__ float As[16][64];
    __shared__ float Bs[16][64];
    const int n0 = blockIdx.x * 64;
    const int tid = threadIdx.x;
    const int tx = tid & 15;
    const int ty = tid >> 4;
    float acc[8][4];
    #pragma unroll
    for (int i = 0; i < 8; i++)
        #pragma unroll
        for (int j = 0; j < 4; j++) acc[i][j] = 0.f;

    for (int k0 = 0; k0 < Un; k0 += 16) {
        #pragma unroll
        for (int l = 0; l < 2; l++) {
            int idx = tid + l * 128;
            int m = idx >> 2;
            int c4 = (idx & 3) << 2;
            float4 v = *(const float4*)(g_x + m * Un + k0 + c4);
            As[c4 + 0][m] = v.x; As[c4 + 1][m] = v.y;
            As[c4 + 2][m] = v.z; As[c4 + 3][m] = v.w;
        }
        #pragma unroll
        for (int l = 0; l < 8; l++) {
            int idx = tid + l * 128;
            int c = idx >> 6;
            int n = idx & 63;
            int ng = n0 + n;
            Bs[c][n] = (ng < Vn) ? W[(size_t)(k0 + c) * Vn + ng] : 0.f;
        }
        __syncthreads();
        #pragma unroll
        for (int k = 0; k < 16; k++) {
            float a[8], bb[4];
            #pragma unroll
            for (int i = 0; i < 8; i++) a[i] = As[k][ty * 8 + i];
            #pragma unroll
            for (int j = 0; j < 4; j++) bb[j] = Bs[k][tx * 4 + j];
            #pragma unroll
            for (int i = 0; i < 8; i++)
                #pragma unroll
                for (int j = 0; j < 4; j++) acc[i][j] += a[i] * bb[j];
        }
        __syncthreads();
    }
    #pragma unroll
    for (int i = 0; i < 8; i++)
        #pragma unroll
        for (int j = 0; j < 4; j++) {
            int m = ty * 8 + i;
            int n = n0 + tx * 4 + j;
            if (n < Vn) g_logits[(size_t)m * Vn + n] = acc[i][j] + db[n];
        }
}

// ---------------- softmax over V -> probs ----------------
__global__ void softmax_v_kernel(float* __restrict__ probs) {
    int b = blockIdx.x;
    int tid = threadIdx.x;
    __shared__ float red[1024];
    const float* lg = g_logits + (size_t)b * Vn;
    float m = -1e30f;
    for (int j = tid; j < Vn; j += 1024) m = fmaxf(m, lg[j]);
    red[tid] = m; __syncthreads();
    for (int o = 512; o > 0; o >>= 1) { if (tid < o) red[tid] = fmaxf(red[tid], red[tid + o]); __syncthreads(); }
    m = red[0]; __syncthreads();
    float sum = 0.f;
    float* pb = probs + (size_t)b * Vn;
    for (int j = tid; j < Vn; j += 1024) {
        float e = expf(lg[j] - m);
        pb[j] = e;
        sum += e;
    }
    red[tid] = sum; __syncthreads();
    for (int o = 512; o > 0; o >>= 1) { if (tid < o) red[tid] += red[tid + o]; __syncthreads(); }
    float inv = 1.f / red[0];
    for (int j = tid; j < Vn; j += 1024) pb[j] *= inv;
}

// ---------------- launch ----------------
extern "C" void kernel_launch(void* const* d_in, const int* in_sizes, int n_in,
                              void* d_out, int out_size) {
    const float* enc = (const float*)d_in[0];
    const float* dec = (const float*)d_in[1];
    const float* qh  = (const float*)d_in[2];
    const float* W1  = (const float*)d_in[3];
    const float* b1  = (const float*)d_in[4];
    const float* W2  = (const float*)d_in[5];
    const float* b2  = (const float*)d_in[6];
    const float* aV  = (const float*)d_in[7];
    const float* abV = (const float*)d_in[8];
    const float* lW  = (const float*)d_in[9];
    const float* lb  = (const float*)d_in[10];
    const float* dW  = (const float*)d_in[11];
    const float* db  = (const float*)d_in[12];

    float* out   = (float*)d_out;
    float* probs = out;                                  // (B,1,V)
    float* hs    = out + (size_t)Bn * Vn;                // (L,B,U)
    float* cs    = hs + (size_t)Ln * Bn * Un;            // (L,B,U)
    float* attnw = cs + (size_t)Ln * Bn * Un;            // (B,S,1)

    static const int RES[8] = {0, 0, 1, 1, 1, 1, 1, 0};

    cudaFuncSetAttribute(score_mma_kernel,
                         cudaFuncAttributeMaxDynamicSharedMemorySize, SC_SMEM);

    copy_x_kernel<<<256, 256>>>(dec);
    conv_w1_kernel<<<dim3(32, 32), dim3(32, 8)>>>(W1);
    q2_kernel<<<dim3(Bn, 8), 128>>>(qh, W2, b1, b2);
    score_mma_kernel<<<dim3(Sn / 64, Bn), 256, SC_SMEM>>>(enc, aV, abV);
    softmax_s_kernel<<<Bn, 256>>>(attnw);
    ctx_kernel<<<dim3(Bn, 8), 128>>>(enc);

    for (int l = 0; l < Ln; l++) {
        lstm_gemm_kernel<<<dim3(64, 4), 128>>>(lW + (size_t)l * 2048 * 4096);
        lstm_act_kernel<<<Bn, 1024>>>(lb + (size_t)l * 4096, hs, cs, l, RES[l]);
    }

    dense_gemm_kernel<<<(Vn + 63) / 64, 128>>>(dW, db);
    softmax_v_kernel<<<Bn, 1024>>>(probs);
}

// round 4
// speedup vs baseline: 3.3235x; 1.1042x over previous
#include <cuda_runtime.h>
#include <cuda_fp16.h>
#include <math.h>
#include <stdint.h>

#define Bn 64
#define Sn 2048
#define Un 1024
#define Vn 50257
#define VnP 50304          // padded to 64
#define Ln 8

// ---------------- scratch (device globals; no allocs allowed) ----------------
__device__ float g_q2[Bn * Un];
__device__ float g_score[Bn * Sn];
__device__ float g_attnw[Bn * Sn];
__device__ float g_ctx[Bn * Un];
__device__ float g_x[Bn * Un];
__device__ float g_z[Bn * 3072];                         // i|g|o gates (f dead)
__device__ float g_logits[(size_t)Bn * Vn];
__device__ __half g_W1h[(size_t)Un * Un];                // W1^T [n][k] fp16
__device__ __half g_inph[2 * Bn * 2048];                 // [plane][b][x|ctx] hi/lo
__device__ __half g_lWh[(size_t)2 * Ln * 3072 * 2048];   // [plane][l][n'][k]
__device__ __half g_dWh[(size_t)2 * VnP * Un];           // [plane][n][k]

#define APLANE ((size_t)Bn * 2048)
#define LPLANE ((size_t)Ln * 3072 * 2048)
#define DPLANE ((size_t)VnP * Un)

// ======================= helpers =======================
__device__ __forceinline__ uint32_t smem_u32(const void* p) {
    uint32_t a;
    asm("{ .reg .u64 t; cvta.to.shared.u64 t, %1; cvt.u32.u64 %0, t; }" : "=r"(a) : "l"(p));
    return a;
}
__device__ __forceinline__ float tanh_fast(float x) {
    float y;
    asm("tanh.approx.f32 %0, %1;" : "=f"(y) : "f"(x));
    return y;
}
#define LDSM4(r0, r1, r2, r3, addr) \
    asm volatile("ldmatrix.sync.aligned.m8n8.x4.shared.b16 {%0,%1,%2,%3}, [%4];" \
                 : "=r"(r0), "=r"(r1), "=r"(r2), "=r"(r3) : "r"(addr))
__device__ __forceinline__ void mma16816(float* d, const uint32_t* a, uint32_t b0, uint32_t b1) {
    asm volatile(
        "mma.sync.aligned.m16n8k16.row.col.f32.f16.f16.f32 "
        "{%0,%1,%2,%3}, {%4,%5,%6,%7}, {%8,%9}, {%0,%1,%2,%3};"
        : "+f"(d[0]), "+f"(d[1]), "+f"(d[2]), "+f"(d[3])
        : "r"(a[0]), "r"(a[1]), "r"(a[2]), "r"(a[3]), "r"(b0), "r"(b1));
}
__device__ __forceinline__ void cp16(uint32_t s, const void* g) {
    asm volatile("cp.async.ca.shared.global [%0], [%1], 16;" :: "r"(s), "l"(g));
}
#define CP_COMMIT() asm volatile("cp.async.commit_group;" ::: "memory")
#define CP_WAIT1() asm volatile("cp.async.wait_group 1;" ::: "memory")
#define CP_WAIT0() asm volatile("cp.async.wait_group 0;" ::: "memory")

// ---------------- init x = dec_input[:,0,:] ----------------
__global__ void copy_x_kernel(const float* __restrict__ dec) {
    int i = blockIdx.x * 256 + threadIdx.x;   // i = b*1024+u
    float v = dec[i];
    g_x[i] = v;
    int b = i >> 10, u = i & 1023;
    __half hi = __float2half_rn(v);
    g_inph[b * 2048 + u] = hi;
    g_inph[APLANE + b * 2048 + u] = __float2half_rn(v - __half2float(hi));
}

// ---------------- convert W1[k][n] -> g_W1h[n][k] fp16 ----------------
__global__ void conv_w1_kernel(const float* __restrict__ W1) {
    __shared__ float t[32][33];
    int n0 = blockIdx.x * 32, k0 = blockIdx.y * 32;
    int x = threadIdx.x, y = threadIdx.y;  // 32x8
    #pragma unroll
    for (int i = 0; i < 32; i += 8)
        t[y + i][x] = W1[(size_t)(k0 + y + i) * Un + n0 + x];
    __syncthreads();
    #pragma unroll
    for (int i = 0; i < 32; i += 8)
        g_W1h[(size_t)(n0 + y + i) * Un + k0 + x] = __float2half_rn(t[x][y + i]);
}

// ---------------- lstm weights: [l][k][4096] -> [plane][l][n'][k], skip f ----------------
__global__ void conv_lstm_kernel(const float* __restrict__ lW) {
    __shared__ float t[32][33];
    int np0 = blockIdx.x * 32;   // n' in [0,3072)
    int k0 = blockIdx.y * 32;
    int l = blockIdx.z;
    int realn = np0 + (np0 >= 1024 ? 1024 : 0);
    int x = threadIdx.x, y = threadIdx.y;
    const float* W = lW + (size_t)l * 2048 * 4096;
    #pragma unroll
    for (int i = 0; i < 32; i += 8)
        t[y + i][x] = W[(size_t)(k0 + y + i) * 4096 + realn + x];
    __syncthreads();
    __half* dst = g_lWh + (size_t)l * 3072 * 2048;
    #pragma unroll
    for (int i = 0; i < 32; i += 8) {
        float w = t[x][y + i];
        __half hi = __float2half_rn(w);
        size_t o = (size_t)(np0 + y + i) * 2048 + k0 + x;
        dst[o] = hi;
        dst[LPLANE + o] = __float2half_rn(w - __half2float(hi));
    }
}

// ---------------- dense weights: [k][Vn] -> [plane][n][k] padded ----------------
__global__ void conv_dense_kernel(const float* __restrict__ dW) {
    __shared__ float t[32][33];
    int n0 = blockIdx.x * 32;    // up to 50304
    int k0 = blockIdx.y * 32;
    int x = threadIdx.x, y = threadIdx.y;
    #pragma unroll
    for (int i = 0; i < 32; i += 8)
        t[y + i][x] = (n0 + x < Vn) ? dW[(size_t)(k0 + y + i) * Vn + n0 + x] : 0.f;
    __syncthreads();
    #pragma unroll
    for (int i = 0; i < 32; i += 8) {
        float w = t[x][y + i];
        __half hi = __float2half_rn(w);
        size_t o = (size_t)(n0 + y + i) * Un + k0 + x;
        g_dWh[o] = hi;
        g_dWh[DPLANE + o] = __float2half_rn(w - __half2float(hi));
    }
}

// ---------------- q2[b,v] = query_h[b]@W2[:,v] + b2[v] + b1[v] ----------------
__global__ void q2_kernel(const float* __restrict__ qh, const float* __restrict__ W2,
                          const float* __restrict__ b1, const float* __restrict__ b2) {
    int b = blockIdx.x;
    int v = blockIdx.y * 128 + threadIdx.x;
    const float* q = qh + b * Un;
    float a0 = 0.f, a1 = 0.f, a2 = 0.f, a3 = 0.f;
    #pragma unroll 1
    for (int k = 0; k < Un; k += 4) {
        a0 += q[k + 0] * W2[(size_t)(k + 0) * Un + v];
        a1 += q[k + 1] * W2[(size_t)(k + 1) * Un + v];
        a2 += q[k + 2] * W2[(size_t)(k + 2) * Un + v];
        a3 += q[k + 3] * W2[(size_t)(k + 3) * Un + v];
    }
    g_q2[b * Un + v] = (a0 + a1) + (a2 + a3) + b1[v] + b2[v];
}

// =================== HMMA fused score GEMM (v2: 2m x 4n warps) ===================
#define SCOFF_A 0           // 64 rows x 2048B = 131072
#define SCOFF_B 131072      // 2 stages x 32768 (256n x 128B)
#define SCOFF_Q2 196608     // 4096
#define SCOFF_AV 200704     // 4096
#define SCOFF_RED 204800    // 4*64*4 = 1024
#define SC_SMEM 205824

__global__ __launch_bounds__(256, 1)
void score_mma_kernel(const float* __restrict__ enc, const float* __restrict__ attnV,
                      const float* __restrict__ attnbV) {
    extern __shared__ char smem[];
    const uint32_t sb = smem_u32(smem);
    const int tid = threadIdx.x;
    const int lane = tid & 31;
    const int wid = tid >> 5;
    const int wm = wid & 1;      // rows wm*32..+32
    const int wn = wid >> 1;     // cols wn*64..+64 of 256-tile
    const int b = blockIdx.y;
    const int s0 = blockIdx.x * 64;

    float* q2s = (float*)(smem + SCOFF_Q2);
    float* avs = (float*)(smem + SCOFF_AV);
    float* red = (float*)(smem + SCOFF_RED);

    for (int i = tid; i < Un; i += 256) {
        q2s[i] = g_q2[b * Un + i];
        avs[i] = attnV[i];
    }

    // A panel: 64x1024 fp32 -> fp16 swizzled (chunk c ^ (r&7))
    const float* encB = enc + ((size_t)b * Sn + s0) * Un;
    #pragma unroll 1
    for (int it = 0; it < 32; it++) {
        int idx = it * 256 + tid;
        int r = idx >> 7;
        int c = idx & 127;
        const float4* src = (const float4*)(encB + (size_t)r * Un + c * 8);
        float4 v0 = src[0], v1 = src[1];
        __half2 h0 = __floats2half2_rn(v0.x, v0.y);
        __half2 h1 = __floats2half2_rn(v0.z, v0.w);
        __half2 h2 = __floats2half2_rn(v1.x, v1.y);
        __half2 h3 = __floats2half2_rn(v1.z, v1.w);
        uint4 u;
        u.x = *reinterpret_cast<uint32_t*>(&h0);
        u.y = *reinterpret_cast<uint32_t*>(&h1);
        u.z = *reinterpret_cast<uint32_t*>(&h2);
        u.w = *reinterpret_cast<uint32_t*>(&h3);
        int cs = c ^ (r & 7);
        *reinterpret_cast<uint4*>(smem + SCOFF_A + r * 2048 + cs * 16) = u;
    }
    __syncthreads();

    // A ldsm bases (2 row-tiles per warp)
    const int ahi = lane >> 4;
    int arow0 = wm * 32 + (lane & 15);
    int arow1 = arow0 + 16;
    const uint32_t ab0 = sb + SCOFF_A + arow0 * 2048;
    const uint32_t ab1 = sb + SCOFF_A + arow1 * 2048;
    const int ax0 = arow0 & 7, ax1 = arow1 & 7;

    // B ldsm bases (4 col-tiles per warp)
    const int bhi = lane >> 4;
    uint32_t bno[4];
    int bxr[4];
    #pragma unroll
    for (int bt = 0; bt < 4; bt++) {
        int bn = wn * 64 + bt * 16 + (lane & 15);
        bno[bt] = bn * 128;
        bxr[bt] = bn & 7;
    }

    const int g = lane >> 2;
    const int t = lane & 3;
    float pa[4];
    #pragma unroll
    for (int i = 0; i < 4; i++) pa[i] = 0.f;

    // B stage loader: 256n x 64k fp16 = 32KB, 2048 chunks, 8/thread
    auto loadB = [&](int nt, int kk, int buf) {
        #pragma unroll
        for (int h = 0; h < 8; h++) {
            int ch = h * 256 + tid;
            int n = ch >> 3;
            int ck = ch & 7;
            uint32_t dst = sb + SCOFF_B + buf * 32768 + n * 128 + ((ck ^ (n & 7)) << 4);
            cp16(dst, g_W1h + (size_t)(nt * 256 + n) * Un + kk * 64 + ck * 8);
        }
    };

    #pragma unroll 1
    for (int nt = 0; nt < 4; nt++) {
        float dacc[16][4];
        #pragma unroll
        for (int i = 0; i < 16; i++)
            #pragma unroll
            for (int j = 0; j < 4; j++) dacc[i][j] = 0.f;

        loadB(nt, 0, 0);
        CP_COMMIT();

        #pragma unroll 1
        for (int kk = 0; kk < 16; kk++) {
            if (kk < 15) {
                loadB(nt, kk + 1, (kk + 1) & 1);
                CP_COMMIT();
                CP_WAIT1();
            } else {
                CP_WAIT0();
            }
            __syncthreads();
            const uint32_t bst = sb + SCOFF_B + (kk & 1) * 32768;
            #pragma unroll
            for (int kk2 = 0; kk2 < 4; kk2++) {
                const int K16 = kk * 4 + kk2;
                uint32_t a0[4], a1[4];
                LDSM4(a0[0], a0[1], a0[2], a0[3], ab0 + (((K16 * 2 + ahi) ^ ax0) << 4));
                LDSM4(a1[0], a1[1], a1[2], a1[3], ab1 + (((K16 * 2 + ahi) ^ ax1) << 4));
                const int ck = kk2 * 2 + bhi;
                #pragma unroll
                for (int bt = 0; bt < 4; bt++) {
                    uint32_t q[4];
                    LDSM4(q[0], q[1], q[2], q[3], bst + bno[bt] + (((ck ^ bxr[bt])) << 4));
                    mma16816(dacc[0 + bt * 2 + 0], a0, q[0], q[2]);
                    mma16816(dacc[0 + bt * 2 + 1], a0, q[1], q[3]);
                    mma16816(dacc[8 + bt * 2 + 0], a1, q[0], q[2]);
                    mma16816(dacc[8 + bt * 2 + 1], a1, q[1], q[3]);
                }
            }
            __syncthreads();
        }
        // epilogue: tanh(D + q2) * attnV, accumulate row partials
        #pragma unroll
        for (int at = 0; at < 2; at++)
            #pragma unroll
            for (int bt = 0; bt < 4; bt++)
                #pragma unroll
                for (int h = 0; h < 2; h++) {
                    const float* dd = dacc[at * 8 + bt * 2 + h];
                    int c0 = nt * 256 + wn * 64 + bt * 16 + h * 8 + 2 * t;
                    float qa = q2s[c0], qb = q2s[c0 + 1];
                    float va = avs[c0], vb = avs[c0 + 1];
                    pa[at * 2 + 0] += tanh_fast(dd[0] + qa) * va + tanh_fast(dd[1] + qb) * vb;
                    pa[at * 2 + 1] += tanh_fast(dd[2] + qa) * va + tanh_fast(dd[3] + qb) * vb;
                }
    }
    // reduce over quad lanes t
    #pragma unroll
    for (int i = 0; i < 4; i++) {
        pa[i] += __shfl_xor_sync(0xffffffffu, pa[i], 1);
        pa[i] += __shfl_xor_sync(0xffffffffu, pa[i], 2);
    }
    if (t == 0) {
        #pragma unroll
        for (int at = 0; at < 2; at++)
            #pragma unroll
            for (int hh = 0; hh < 2; hh++)
                red[wn * 64 + wm * 32 + at * 16 + hh * 8 + g] = pa[at * 2 + hh];
    }
    __syncthreads();
    if (tid < 64) {
        float s = red[tid] + red[64 + tid] + red[128 + tid] + red[192 + tid] + attnbV[0];
        g_score[b * Sn + s0 + tid] = s;
    }
}

// ---------------- softmax over S ----------------
__global__ void softmax_s_kernel(float* __restrict__ out_attnw) {
    int b = blockIdx.x;
    int tid = threadIdx.x;
    __shared__ float red[256];
    float m = -1e30f;
    for (int s = tid; s < Sn; s += 256) m = fmaxf(m, g_score[b * Sn + s]);
    red[tid] = m; __syncthreads();
    for (int o = 128; o > 0; o >>= 1) { if (tid < o) red[tid] = fmaxf(red[tid], red[tid + o]); __syncthreads(); }
    m = red[0]; __syncthreads();
    float sum = 0.f;
    for (int s = tid; s < Sn; s += 256) {
        float e = expf(g_score[b * Sn + s] - m);
        g_attnw[b * Sn + s] = e;
        sum += e;
    }
    red[tid] = sum; __syncthreads();
    for (int o = 128; o > 0; o >>= 1) { if (tid < o) red[tid] += red[tid + o]; __syncthreads(); }
    float inv = 1.f / red[0];
    for (int s = tid; s < Sn; s += 256) {
        float w = g_attnw[b * Sn + s] * inv;
        g_attnw[b * Sn + s] = w;
        out_attnw[b * Sn + s] = w;
    }
}

// ---------------- ctx[b,u] = sum_s attn_w[b,s]*enc[b,s,u]; writes fp16 planes ----------------
__global__ void ctx_kernel(const float* __restrict__ enc) {
    int b = blockIdx.x;
    int u = blockIdx.y * 128 + threadIdx.x;
    const float* e = enc + (size_t)b * Sn * Un + u;
    const float* w = g_attnw + b * Sn;
    float a0 = 0.f, a1 = 0.f, a2 = 0.f, a3 = 0.f;
    for (int s = 0; s < Sn; s += 4) {
        a0 += w[s + 0] * e[(size_t)(s + 0) * Un];
        a1 += w[s + 1] * e[(size_t)(s + 1) * Un];
        a2 += w[s + 2] * e[(size_t)(s + 2) * Un];
        a3 += w[s + 3] * e[(size_t)(s + 3) * Un];
    }
    float c = (a0 + a1) + (a2 + a3);
    g_ctx[b * Un + u] = c;
    __half hi = __float2half_rn(c);
    g_inph[b * 2048 + 1024 + u] = hi;
    g_inph[APLANE + b * 2048 + 1024 + u] = __float2half_rn(c - __half2float(hi));
}

// =================== split-fp16 HMMA GEMM (LSTM z / dense logits) ===================
// C[64 x n] = A @ B^T via 3 segments: Ah*Bh + Ah*Bl + Al*Bh (fp32 accum)
// A: g_inph-style [plane][64][lda] fp16; B: [plane][n][K] fp16. n-tile 64/CTA.
__global__ __launch_bounds__(128)
void mma3_gemm_kernel(const __half* __restrict__ A, size_t a_plane, int lda,
                      const __half* __restrict__ Bt, size_t b_plane, int K,
                      float* __restrict__ C, int ldc,
                      const float* __restrict__ bias, int nvalid) {
    __shared__ __align__(128) char gsm[32768];   // A 2x8KB @0, B 2x8KB @16384
    const uint32_t sb = smem_u32(gsm);
    const int tid = threadIdx.x;
    const int lane = tid & 31;
    const int wid = tid >> 5;
    const int wm = wid & 1;
    const int wn = wid >> 1;     // 0..1
    const int n0 = blockIdx.x * 64;
    const int segkk = K >> 6;
    const int nkk = segkk * 3;

    auto loadStage = [&](int kk, int buf) {
        int seg = (kk >= 2 * segkk) ? 2 : (kk >= segkk ? 1 : 0);
        int kloc = kk - seg * segkk;
        const __half* Ab = A + (seg == 2 ? a_plane : 0);
        const __half* Bb = Bt + (seg == 1 ? b_plane : 0);
        #pragma unroll
        for (int j = 0; j < 4; j++) {
            int ch = j * 128 + tid;
            int m = ch >> 3;
            int ck = ch & 7;
            cp16(sb + buf * 8192 + m * 128 + ((ck ^ (m & 7)) << 4),
                 Ab + (size_t)m * lda + kloc * 64 + ck * 8);
        }
        #pragma unroll
        for (int j = 0; j < 4; j++) {
            int ch = j * 128 + tid;
            int n = ch >> 3;
            int ck = ch & 7;
            cp16(sb + 16384 + buf * 8192 + n * 128 + ((ck ^ (n & 7)) << 4),
                 Bb + (size_t)(n0 + n) * K + kloc * 64 + ck * 8);
        }
    };

    float dacc[8][4];
    #pragma unroll
    for (int i = 0; i < 8; i++)
        #pragma unroll
        for (int j = 0; j < 4; j++) dacc[i][j] = 0.f;

    const int hi = lane >> 4;
    const int arow0 = wm * 32 + (lane & 15);
    const int arow1 = arow0 + 16;
    const int bn0 = wn * 32 + (lane & 15);
    const int bn1 = bn0 + 16;

    loadStage(0, 0);
    CP_COMMIT();

    #pragma unroll 1
    for (int kk = 0; kk < nkk; kk++) {
        if (kk < nkk - 1) {
            loadStage(kk + 1, (kk + 1) & 1);
            CP_COMMIT();
            CP_WAIT1();
        } else {
            CP_WAIT0();
        }
        __syncthreads();
        const uint32_t ast = sb + (kk & 1) * 8192;
        const uint32_t bst = sb + 16384 + (kk & 1) * 8192;
        #pragma unroll
        for (int kk2 = 0; kk2 < 4; kk2++) {
            const int ck = kk2 * 2 + hi;
            uint32_t a0[4], a1[4], q0[4], q1[4];
            LDSM4(a0[0], a0[1], a0[2], a0[3], ast + arow0 * 128 + ((ck ^ (arow0 & 7)) << 4));
            LDSM4(a1[0], a1[1], a1[2], a1[3], ast + arow1 * 128 + ((ck ^ (arow1 & 7)) << 4));
            LDSM4(q0[0], q0[1], q0[2], q0[3], bst + bn0 * 128 + ((ck ^ (bn0 & 7)) << 4));
            LDSM4(q1[0], q1[1], q1[2], q1[3], bst + bn1 * 128 + ((ck ^ (bn1 & 7)) << 4));
            mma16816(dacc[0], a0, q0[0], q0[2]);
            mma16816(dacc[1], a0, q0[1], q0[3]);
            mma16816(dacc[2], a0, q1[0], q1[2]);
            mma16816(dacc[3], a0, q1[1], q1[3]);
            mma16816(dacc[4], a1, q0[0], q0[2]);
            mma16816(dacc[5], a1, q0[1], q0[3]);
            mma16816(dacc[6], a1, q1[0], q1[2]);
            mma16816(dacc[7], a1, q1[1], q1[3]);
        }
        __syncthreads();
    }

    const int g = lane >> 2;
    const int t = lane & 3;
    #pragma unroll
    for (int at = 0; at < 2; at++)
        #pragma unroll
        for (int bt = 0; bt < 2; bt++)
            #pragma unroll
            for (int h = 0; h < 2; h++) {
                const float* dd = dacc[at * 4 + bt * 2 + h];
                int c0 = n0 + wn * 32 + bt * 16 + h * 8 + 2 * t;
                int r0 = wm * 32 + at * 16 + g;
                int r1 = r0 + 8;
                if (c0 < nvalid) {
                    float bb = bias ? bias[c0] : 0.f;
                    C[(size_t)r0 * ldc + c0] = dd[0] + bb;
                    C[(size_t)r1 * ldc + c0] = dd[2] + bb;
                }
                if (c0 + 1 < nvalid) {
                    float bb = bias ? bias[c0 + 1] : 0.f;
                    C[(size_t)r0 * ldc + c0 + 1] = dd[1] + bb;
                    C[(size_t)r1 * ldc + c0 + 1] = dd[3] + bb;
                }
            }
}

// ---------------- LSTM activation ----------------
__global__ void lstm_act_kernel(const float* __restrict__ lb,
                                float* __restrict__ hs, float* __restrict__ cs,
                                int layer, int residual) {
    int b = blockIdx.x;
    int u = threadIdx.x;
    const float* z = g_z + b * 3072;
    float zi = z[u] + lb[u];
    float zg = z[1024 + u] + lb[2048 + u];
    float zo = z[2048 + u] + lb[3072 + u];
    float c = (1.f / (1.f + expf(-zi))) * tanhf(zg);
    float h = (1.f / (1.f + expf(-zo))) * tanhf(c);
    size_t o = ((size_t)layer * Bn + b) * Un + u;
    hs[o] = h;
    cs[o] = c;
    float xo = g_x[b * Un + u];
    float xn = residual ? (h + xo) : h;
    g_x[b * Un + u] = xn;
    __half hhi = __float2half_rn(xn);
    g_inph[b * 2048 + u] = hhi;
    g_inph[APLANE + b * 2048 + u] = __float2half_rn(xn - __half2float(hhi));
}

// ---------------- softmax over V -> probs ----------------
__global__ void softmax_v_kernel(float* __restrict__ probs) {
    int b = blockIdx.x;
    int tid = threadIdx.x;
    __shared__ float red[1024];
    const float* lg = g_logits + (size_t)b * Vn;
    float m = -1e30f;
    for (int j = tid; j < Vn; j += 1024) m = fmaxf(m, lg[j]);
    red[tid] = m; __syncthreads();
    for (int o = 512; o > 0; o >>= 1) { if (tid < o) red[tid] = fmaxf(red[tid], red[tid + o]); __syncthreads(); }
    m = red[0]; __syncthreads();
    float sum = 0.f;
    float* pb = probs + (size_t)b * Vn;
    for (int j = tid; j < Vn; j += 1024) {
        float e = expf(lg[j] - m);
        pb[j] = e;
        sum += e;
    }
    red[tid] = sum; __syncthreads();
    for (int o = 512; o > 0; o >>= 1) { if (tid < o) red[tid] += red[tid + o]; __syncthreads(); }
    float inv = 1.f / red[0];
    for (int j = tid; j < Vn; j += 1024) pb[j] *= inv;
}

// ---------------- launch ----------------
extern "C" void kernel_launch(void* const* d_in, const int* in_sizes, int n_in,
                              void* d_out, int out_size) {
    const float* enc = (const float*)d_in[0];
    const float* dec = (const float*)d_in[1];
    const float* qh  = (const float*)d_in[2];
    const float* W1  = (const float*)d_in[3];
    const float* b1  = (const float*)d_in[4];
    const float* W2  = (const float*)d_in[5];
    const float* b2  = (const float*)d_in[6];
    const float* aV  = (const float*)d_in[7];
    const float* abV = (const float*)d_in[8];
    const float* lW  = (const float*)d_in[9];
    const float* lb  = (const float*)d_in[10];
    const float* dW  = (const float*)d_in[11];
    const float* db  = (const float*)d_in[12];

    float* out   = (float*)d_out;
    float* probs = out;
    float* hs    = out + (size_t)Bn * Vn;
    float* cs    = hs + (size_t)Ln * Bn * Un;
    float* attnw = cs + (size_t)Ln * Bn * Un;

    static const int RES[8] = {0, 0, 1, 1, 1, 1, 1, 0};

    cudaFuncSetAttribute(score_mma_kernel,
                         cudaFuncAttributeMaxDynamicSharedMemorySize, SC_SMEM);

    // resolve device symbol addresses (host side)
    __half *p_inph, *p_lWh, *p_dWh;
    float *p_z, *p_logits;
    cudaGetSymbolAddress((void**)&p_inph, g_inph);
    cudaGetSymbolAddress((void**)&p_lWh, g_lWh);
    cudaGetSymbolAddress((void**)&p_dWh, g_dWh);
    cudaGetSymbolAddress((void**)&p_z, g_z);
    cudaGetSymbolAddress((void**)&p_logits, g_logits);

    copy_x_kernel<<<256, 256>>>(dec);
    conv_w1_kernel<<<dim3(32, 32), dim3(32, 8)>>>(W1);
    conv_lstm_kernel<<<dim3(96, 64, 8), dim3(32, 8)>>>(lW);
    conv_dense_kernel<<<dim3(VnP / 32, 32), dim3(32, 8)>>>(dW);
    q2_kernel<<<dim3(Bn, 8), 128>>>(qh, W2, b1, b2);
    score_mma_kernel<<<dim3(Sn / 64, Bn), 256, SC_SMEM>>>(enc, aV, abV);
    softmax_s_kernel<<<Bn, 256>>>(attnw);
    ctx_kernel<<<dim3(Bn, 8), 128>>>(enc);

    for (int l = 0; l < Ln; l++) {
        mma3_gemm_kernel<<<48, 128>>>(p_inph, APLANE, 2048,
                                      p_lWh + (size_t)l * 3072 * 2048, LPLANE, 2048,
                                      p_z, 3072, nullptr, 3072);
        lstm_act_kernel<<<Bn, 1024>>>(lb + (size_t)l * 4096, hs, cs, l, RES[l]);
    }

    mma3_gemm_kernel<<<VnP / 64, 128>>>(p_inph, APLANE, 2048,
                                        p_dWh, DPLANE, 1024,
                                        p_logits, Vn, db, Vn);
    softmax_v_kernel<<<Bn, 1024>>>(probs);
}

// round 5
// speedup vs baseline: 4.1231x; 1.2406x over previous
#include <cuda_runtime.h>
#include <cuda_fp16.h>
#include <math.h>
#include <stdint.h>

#define Bn 64
#define Sn 2048
#define Un 1024
#define Vn 50257
#define VnP 50304
#define Ln 8

// ---------------- scratch (device globals; no allocs allowed) ----------------
__device__ float g_q2[Bn * Un];
__device__ float g_score[Bn * Sn];
__device__ float g_attnw[Bn * Sn];
__device__ float g_x[Bn * Un];
__device__ float g_zp8[8 * Bn * 3072];                 // k-split partials (i|g|o)
__device__ float g_logits[(size_t)Bn * Vn];
__device__ __half g_W1h[(size_t)Un * Un];              // W1^T [n][k] fp16
__device__ __half g_ench[(size_t)Bn * Sn * Un];        // enc as fp16
__device__ __half g_inph[2 * Bn * 2048];               // [plane][b][x|ctx] hi/lo

#define APLANE ((size_t)Bn * 2048)

// ======================= helpers =======================
__device__ __forceinline__ uint32_t smem_u32(const void* p) {
    uint32_t a;
    asm("{ .reg .u64 t; cvta.to.shared.u64 t, %1; cvt.u32.u64 %0, t; }" : "=r"(a) : "l"(p));
    return a;
}
__device__ __forceinline__ float tanh_fast(float x) {
    float y;
    asm("tanh.approx.f32 %0, %1;" : "=f"(y) : "f"(x));
    return y;
}
#define LDSM4(r0, r1, r2, r3, addr) \
    asm volatile("ldmatrix.sync.aligned.m8n8.x4.shared.b16 {%0,%1,%2,%3}, [%4];" \
                 : "=r"(r0), "=r"(r1), "=r"(r2), "=r"(r3) : "r"(addr))
#define LDSM4T(r0, r1, r2, r3, addr) \
    asm volatile("ldmatrix.sync.aligned.m8n8.x4.trans.shared.b16 {%0,%1,%2,%3}, [%4];" \
                 : "=r"(r0), "=r"(r1), "=r"(r2), "=r"(r3) : "r"(addr))
__device__ __forceinline__ void mma16816(float* d, const uint32_t* a, uint32_t b0, uint32_t b1) {
    asm volatile(
        "mma.sync.aligned.m16n8k16.row.col.f32.f16.f16.f32 "
        "{%0,%1,%2,%3}, {%4,%5,%6,%7}, {%8,%9}, {%0,%1,%2,%3};"
        : "+f"(d[0]), "+f"(d[1]), "+f"(d[2]), "+f"(d[3])
        : "r"(a[0]), "r"(a[1]), "r"(a[2]), "r"(a[3]), "r"(b0), "r"(b1));
}
__device__ __forceinline__ void cp16(uint32_t s, const void* g) {
    asm volatile("cp.async.ca.shared.global [%0], [%1], 16;" :: "r"(s), "l"(g));
}
#define CP_COMMIT() asm volatile("cp.async.commit_group;" ::: "memory")
#define CP_WAIT1() asm volatile("cp.async.wait_group 1;" ::: "memory")
#define CP_WAIT0() asm volatile("cp.async.wait_group 0;" ::: "memory")

// pack 8 floats -> hi uint4 and lo uint4 (lo = v - hi)
__device__ __forceinline__ void split8(const float* v, uint4& hi4, uint4& lo4) {
    __half2 h[4], l[4];
    #pragma unroll
    for (int i = 0; i < 4; i++) {
        h[i] = __floats2half2_rn(v[2 * i], v[2 * i + 1]);
        float2 hf = __half22float2(h[i]);
        l[i] = __floats2half2_rn(v[2 * i] - hf.x, v[2 * i + 1] - hf.y);
    }
    hi4.x = *reinterpret_cast<uint32_t*>(&h[0]);
    hi4.y = *reinterpret_cast<uint32_t*>(&h[1]);
    hi4.z = *reinterpret_cast<uint32_t*>(&h[2]);
    hi4.w = *reinterpret_cast<uint32_t*>(&h[3]);
    lo4.x = *reinterpret_cast<uint32_t*>(&l[0]);
    lo4.y = *reinterpret_cast<uint32_t*>(&l[1]);
    lo4.z = *reinterpret_cast<uint32_t*>(&l[2]);
    lo4.w = *reinterpret_cast<uint32_t*>(&l[3]);
}

// ---------------- init x = dec_input[:,0,:] ----------------
__global__ void copy_x_kernel(const float* __restrict__ dec) {
    int i = blockIdx.x * 256 + threadIdx.x;
    float v = dec[i];
    g_x[i] = v;
    int b = i >> 10, u = i & 1023;
    __half hi = __float2half_rn(v);
    g_inph[b * 2048 + u] = hi;
    g_inph[APLANE + b * 2048 + u] = __float2half_rn(v - __half2float(hi));
}

// ---------------- enc fp32 -> fp16 streaming ----------------
__global__ void ench_kernel(const float* __restrict__ enc) {
    size_t i = ((size_t)blockIdx.x * 256 + threadIdx.x) * 8;
    float4 v0 = *(const float4*)(enc + i);
    float4 v1 = *(const float4*)(enc + i + 4);
    __half2 h0 = __floats2half2_rn(v0.x, v0.y);
    __half2 h1 = __floats2half2_rn(v0.z, v0.w);
    __half2 h2 = __floats2half2_rn(v1.x, v1.y);
    __half2 h3 = __floats2half2_rn(v1.z, v1.w);
    uint4 u;
    u.x = *reinterpret_cast<uint32_t*>(&h0);
    u.y = *reinterpret_cast<uint32_t*>(&h1);
    u.z = *reinterpret_cast<uint32_t*>(&h2);
    u.w = *reinterpret_cast<uint32_t*>(&h3);
    *reinterpret_cast<uint4*>(g_ench + i) = u;
}

// ---------------- convert W1[k][n] -> g_W1h[n][k] fp16 ----------------
__global__ void conv_w1_kernel(const float* __restrict__ W1) {
    __shared__ float t[32][33];
    int n0 = blockIdx.x * 32, k0 = blockIdx.y * 32;
    int x = threadIdx.x, y = threadIdx.y;
    #pragma unroll
    for (int i = 0; i < 32; i += 8)
        t[y + i][x] = W1[(size_t)(k0 + y + i) * Un + n0 + x];
    __syncthreads();
    #pragma unroll
    for (int i = 0; i < 32; i += 8)
        g_W1h[(size_t)(n0 + y + i) * Un + k0 + x] = __float2half_rn(t[x][y + i]);
}

// ---------------- q2[b,v] = query_h[b]@W2[:,v] + b2[v] + b1[v] ----------------
__global__ void q2_kernel(const float* __restrict__ qh, const float* __restrict__ W2,
                          const float* __restrict__ b1, const float* __restrict__ b2) {
    int b = blockIdx.x;
    int v = blockIdx.y * 128 + threadIdx.x;
    const float* q = qh + b * Un;
    float a0 = 0.f, a1 = 0.f, a2 = 0.f, a3 = 0.f;
    #pragma unroll 1
    for (int k = 0; k < Un; k += 4) {
        a0 += q[k + 0] * W2[(size_t)(k + 0) * Un + v];
        a1 += q[k + 1] * W2[(size_t)(k + 1) * Un + v];
        a2 += q[k + 2] * W2[(size_t)(k + 2) * Un + v];
        a3 += q[k + 3] * W2[(size_t)(k + 3) * Un + v];
    }
    g_q2[b * Un + v] = (a0 + a1) + (a2 + a3) + b1[v] + b2[v];
}

// =================== HMMA fused score GEMM (512 threads, 16 warps) ===================
#define SCOFF_A 0           // 64 x 2048B = 131072
#define SCOFF_B 131072      // 2 x 32768 (256n x 128B)
#define SCOFF_Q2 196608
#define SCOFF_AV 200704
#define SCOFF_RED 204800    // 256 floats
#define SC_SMEM 205824

__global__ __launch_bounds__(512, 1)
void score_mma_kernel(const float* __restrict__ attnV, const float* __restrict__ attnbV) {
    extern __shared__ char smem[];
    const uint32_t sb = smem_u32(smem);
    const int tid = threadIdx.x;
    const int lane = tid & 31;
    const int wid = tid >> 5;
    const int wm = wid & 3;      // rows wm*16..+16
    const int wn = wid >> 2;     // cols wn*64..+64 of 256-tile
    const int b = blockIdx.y;
    const int s0 = blockIdx.x * 64;

    float* q2s = (float*)(smem + SCOFF_Q2);
    float* avs = (float*)(smem + SCOFF_AV);
    float* red = (float*)(smem + SCOFF_RED);

    for (int i = tid; i < Un; i += 512) {
        q2s[i] = g_q2[b * Un + i];
        avs[i] = attnV[i];
    }

    // A panel: 64x1024 fp16, contiguous in g_ench, cp.async w/ swizzle
    const __half* panel = g_ench + ((size_t)b * Sn + s0) * Un;
    #pragma unroll
    for (int it = 0; it < 16; it++) {
        int id = it * 512 + tid;       // chunk id, 8192 total
        int r = id >> 7;
        int c = id & 127;
        cp16(sb + SCOFF_A + r * 2048 + ((c ^ (r & 7)) << 4),
             panel + (size_t)id * 8);
    }

    // B stage loader: 256n x 64k fp16 = 32KB, 2048 chunks, 4/thread
    auto loadB = [&](int nt, int kk, int buf) {
        #pragma unroll
        for (int h = 0; h < 4; h++) {
            int ch = h * 512 + tid;
            int n = ch >> 3;
            int ck = ch & 7;
            cp16(sb + SCOFF_B + buf * 32768 + n * 128 + ((ck ^ (n & 7)) << 4),
                 g_W1h + (size_t)(nt * 256 + n) * Un + kk * 64 + ck * 8);
        }
    };

    // A ldsm base
    const int ahi = lane >> 4;
    const int arow = wm * 16 + (lane & 15);
    const uint32_t abase = sb + SCOFF_A + arow * 2048;
    const int axr = arow & 7;

    // B ldsm bases (4 col-tiles of 16)
    const int bhi = lane >> 4;
    uint32_t bno[4];
    int bxr[4];
    #pragma unroll
    for (int bt = 0; bt < 4; bt++) {
        int bn = wn * 64 + bt * 16 + (lane & 15);
        bno[bt] = bn * 128;
        bxr[bt] = bn & 7;
    }

    const int g = lane >> 2;
    const int t = lane & 3;
    float p0 = 0.f, p1 = 0.f;

    bool first = true;
    #pragma unroll 1
    for (int nt = 0; nt < 4; nt++) {
        float dacc[8][4];
        #pragma unroll
        for (int i = 0; i < 8; i++)
            #pragma unroll
            for (int j = 0; j < 4; j++) dacc[i][j] = 0.f;

        loadB(nt, 0, 0);
        CP_COMMIT();               // first commit also covers the A panel

        #pragma unroll 1
        for (int kk = 0; kk < 16; kk++) {
            if (kk < 15) {
                loadB(nt, kk + 1, (kk + 1) & 1);
                CP_COMMIT();
                CP_WAIT1();
            } else {
                CP_WAIT0();
            }
            __syncthreads();
            (void)first;
            const uint32_t bst = sb + SCOFF_B + (kk & 1) * 32768;
            #pragma unroll
            for (int kk2 = 0; kk2 < 4; kk2++) {
                const int K16 = kk * 4 + kk2;
                uint32_t a[4];
                LDSM4(a[0], a[1], a[2], a[3], abase + (((K16 * 2 + ahi) ^ axr) << 4));
                const int ck = kk2 * 2 + bhi;
                #pragma unroll
                for (int bt = 0; bt < 4; bt++) {
                    uint32_t q[4];
                    LDSM4(q[0], q[1], q[2], q[3], bst + bno[bt] + ((ck ^ bxr[bt]) << 4));
                    mma16816(dacc[bt * 2 + 0], a, q[0], q[2]);
                    mma16816(dacc[bt * 2 + 1], a, q[1], q[3]);
                }
            }
            __syncthreads();
        }
        // epilogue: tanh(D + q2) * attnV
        #pragma unroll
        for (int bt = 0; bt < 4; bt++)
            #pragma unroll
            for (int h = 0; h < 2; h++) {
                const float* dd = dacc[bt * 2 + h];
                int c0 = nt * 256 + wn * 64 + bt * 16 + h * 8 + 2 * t;
                float qa = q2s[c0], qb = q2s[c0 + 1];
                float va = avs[c0], vb = avs[c0 + 1];
                p0 += tanh_fast(dd[0] + qa) * va + tanh_fast(dd[1] + qb) * vb;
                p1 += tanh_fast(dd[2] + qa) * va + tanh_fast(dd[3] + qb) * vb;
            }
    }
    p0 += __shfl_xor_sync(0xffffffffu, p0, 1);
    p0 += __shfl_xor_sync(0xffffffffu, p0, 2);
    p1 += __shfl_xor_sync(0xffffffffu, p1, 1);
    p1 += __shfl_xor_sync(0xffffffffu, p1, 2);
    if (t == 0) {
        red[wn * 64 + wm * 16 + g] = p0;
        red[wn * 64 + wm * 16 + 8 + g] = p1;
    }
    __syncthreads();
    if (tid < 64) {
        g_score[b * Sn + s0 + tid] =
            red[tid] + red[64 + tid] + red[128 + tid] + red[192 + tid] + attnbV[0];
    }
}

// ---------------- softmax over S ----------------
__global__ void softmax_s_kernel(float* __restrict__ out_attnw) {
    int b = blockIdx.x;
    int tid = threadIdx.x;
    __shared__ float red[256];
    float m = -1e30f;
    for (int s = tid; s < Sn; s += 256) m = fmaxf(m, g_score[b * Sn + s]);
    red[tid] = m; __syncthreads();
    for (int o = 128; o > 0; o >>= 1) { if (tid < o) red[tid] = fmaxf(red[tid], red[tid + o]); __syncthreads(); }
    m = red[0]; __syncthreads();
    float sum = 0.f;
    for (int s = tid; s < Sn; s += 256) {
        float e = expf(g_score[b * Sn + s] - m);
        g_attnw[b * Sn + s] = e;
        sum += e;
    }
    red[tid] = sum; __syncthreads();
    for (int o = 128; o > 0; o >>= 1) { if (tid < o) red[tid] += red[tid + o]; __syncthreads(); }
    float inv = 1.f / red[0];
    for (int s = tid; s < Sn; s += 256) {
        float w = g_attnw[b * Sn + s] * inv;
        g_attnw[b * Sn + s] = w;
        out_attnw[b * Sn + s] = w;
    }
}

// ---------------- ctx[b,u] = sum_s attn_w[b,s]*ench[b,s,u]; write fp16 planes ----------------
__global__ void ctx_kernel() {
    int b = blockIdx.x;
    int u = blockIdx.y * 128 + threadIdx.x;
    const __half* e = g_ench + (size_t)b * Sn * Un + u;
    const float* w = g_attnw + b * Sn;
    float a0 = 0.f, a1 = 0.f, a2 = 0.f, a3 = 0.f;
    for (int s = 0; s < Sn; s += 4) {
        a0 += w[s + 0] * __half2float(e[(size_t)(s + 0) * Un]);
        a1 += w[s + 1] * __half2float(e[(size_t)(s + 1) * Un]);
        a2 += w[s + 2] * __half2float(e[(size_t)(s + 2) * Un]);
        a3 += w[s + 3] * __half2float(e[(size_t)(s + 3) * Un]);
    }
    float c = (a0 + a1) + (a2 + a3);
    __half hi = __float2half_rn(c);
    g_inph[b * 2048 + 1024 + u] = hi;
    g_inph[APLANE + b * 2048 + 1024 + u] = __float2half_rn(c - __half2float(hi));
}

// =================== LSTM GEMM: fused fp32-weight split-fp16 HMMA ===================
// zpart[ks][64][3072] partials; grid (48 n-tiles, 8 k-splits), 128 threads.
__global__ __launch_bounds__(128)
void lstm_mma_kernel(const float* __restrict__ W) {
    __shared__ __align__(128) char sm[32768];   // Ah@0 Al@8192 Bh@16384 Bl@24576
    const uint32_t sb = smem_u32(sm);
    const int tid = threadIdx.x, lane = tid & 31, wid = tid >> 5;
    const int wm = wid & 1, wn = wid >> 1;
    const int nt = blockIdx.x;
    const int ks = blockIdx.y;
    const int k0 = ks * 256;
    const int wcol0 = nt * 64 + (nt >= 16 ? 1024 : 0);
    const int zcol0 = nt * 64;

    float dacc[8][4];
    #pragma unroll
    for (int i = 0; i < 8; i++)
        #pragma unroll
        for (int j = 0; j < 4; j++) dacc[i][j] = 0.f;

    const int hi16 = lane >> 4;
    const int g8 = lane >> 3;
    const int r8 = lane & 7;
    const int arow0 = wm * 32 + (lane & 15);
    const int arow1 = arow0 + 16;

    #pragma unroll 1
    for (int kk = 0; kk < 4; kk++) {
        const int kg = k0 + kk * 64;
        __syncthreads();
        // B: W fp32 [64k][64n] -> Bh/Bl smem [k][n]
        #pragma unroll
        for (int j = 0; j < 4; j++) {
            int ch = j * 128 + tid;
            int k = ch >> 3, c = ch & 7;
            const float* src = W + (size_t)(kg + k) * 4096 + wcol0 + c * 8;
            float v[8];
            float4 s0 = *(const float4*)src;
            float4 s1 = *(const float4*)(src + 4);
            v[0] = s0.x; v[1] = s0.y; v[2] = s0.z; v[3] = s0.w;
            v[4] = s1.x; v[5] = s1.y; v[6] = s1.z; v[7] = s1.w;
            uint4 hi4, lo4;
            split8(v, hi4, lo4);
            int off = k * 128 + ((c ^ (k & 7)) << 4);
            *(uint4*)(sm + 16384 + off) = hi4;
            *(uint4*)(sm + 24576 + off) = lo4;
        }
        // A: cp.async hi/lo tiles from g_inph
        #pragma unroll
        for (int j = 0; j < 8; j++) {
            int ch = j * 128 + tid;
            int plane = ch >> 9, cc = ch & 511;
            int m = cc >> 3, c = cc & 7;
            cp16(sb + plane * 8192 + m * 128 + ((c ^ (m & 7)) << 4),
                 g_inph + (size_t)plane * APLANE + (size_t)m * 2048 + kg + c * 8);
        }
        CP_COMMIT(); CP_WAIT0();
        __syncthreads();
        // 3 segments: Ah*Bh, Ah*Bl, Al*Bh
        #pragma unroll
        for (int seg = 0; seg < 3; seg++) {
            const uint32_t abase = sb + (seg == 2 ? 8192 : 0);
            const uint32_t bbase = sb + 16384 + (seg == 1 ? 8192 : 0);
            #pragma unroll
            for (int kk2 = 0; kk2 < 4; kk2++) {
                uint32_t a0[4], a1[4];
                int ck = kk2 * 2 + hi16;
                LDSM4(a0[0], a0[1], a0[2], a0[3],
                      abase + arow0 * 128 + ((ck ^ (arow0 & 7)) << 4));
                LDSM4(a1[0], a1[1], a1[2], a1[3],
                      abase + arow1 * 128 + ((ck ^ (arow1 & 7)) << 4));
                int kloc = kk2 * 16 + (g8 & 1) * 8 + r8;
                #pragma unroll
                for (int bt = 0; bt < 2; bt++) {
                    int nchunk = wn * 4 + bt * 2 + (g8 >> 1);
                    uint32_t q[4];
                    LDSM4T(q[0], q[1], q[2], q[3],
                           bbase + kloc * 128 + ((nchunk ^ (kloc & 7)) << 4));
                    mma16816(dacc[0 + bt * 2 + 0], a0, q[0], q[1]);
                    mma16816(dacc[0 + bt * 2 + 1], a0, q[2], q[3]);
                    mma16816(dacc[4 + bt * 2 + 0], a1, q[0], q[1]);
                    mma16816(dacc[4 + bt * 2 + 1], a1, q[2], q[3]);
                }
            }
        }
    }
    const int g = lane >> 2;
    const int t = lane & 3;
    float* zp = g_zp8 + (size_t)ks * Bn * 3072;
    #pragma unroll
    for (int at = 0; at < 2; at++)
        #pragma unroll
        for (int bt = 0; bt < 2; bt++)
            #pragma unroll
            for (int h = 0; h < 2; h++) {
                const float* dd = dacc[at * 4 + bt * 2 + h];
                int c0 = zcol0 + wn * 32 + bt * 16 + h * 8 + 2 * t;
                int r0 = wm * 32 + at * 16 + g;
                zp[(size_t)r0 * 3072 + c0] = dd[0];
                zp[(size_t)r0 * 3072 + c0 + 1] = dd[1];
                zp[(size_t)(r0 + 8) * 3072 + c0] = dd[2];
                zp[(size_t)(r0 + 8) * 3072 + c0 + 1] = dd[3];
            }
}

// ---------------- LSTM activation: sum 8 partials + bias -> c,h; update x ----------------
__global__ void lstm_act_kernel(const float* __restrict__ lb,
                                float* __restrict__ hs, float* __restrict__ cs,
                                int layer, int residual) {
    int b = blockIdx.x;
    int u = threadIdx.x;
    float zi = lb[u], zg = lb[2048 + u], zo = lb[3072 + u];
    #pragma unroll
    for (int ks = 0; ks < 8; ks++) {
        const float* zp = g_zp8 + ((size_t)ks * Bn + b) * 3072;
        zi += zp[u];
        zg += zp[1024 + u];
        zo += zp[2048 + u];
    }
    float c = (1.f / (1.f + expf(-zi))) * tanhf(zg);
    float h = (1.f / (1.f + expf(-zo))) * tanhf(c);
    size_t o = ((size_t)layer * Bn + b) * Un + u;
    hs[o] = h;
    cs[o] = c;
    float xo = g_x[b * Un + u];
    float xn = residual ? (h + xo) : h;
    g_x[b * Un + u] = xn;
    __half hhi = __float2half_rn(xn);
    g_inph[b * 2048 + u] = hhi;
    g_inph[APLANE + b * 2048 + u] = __float2half_rn(xn - __half2float(hhi));
}

// =================== dense GEMM: fused fp32-weight split-fp16 HMMA ===================
__global__ __launch_bounds__(128)
void dense_mma_kernel(const float* __restrict__ W, const float* __restrict__ db) {
    __shared__ __align__(128) char sm[32768];
    const uint32_t sb = smem_u32(sm);
    const int tid = threadIdx.x, lane = tid & 31, wid = tid >> 5;
    const int wm = wid & 1, wn = wid >> 1;
    const int n0 = blockIdx.x * 64;

    float dacc[8][4];
    #pragma unroll
    for (int i = 0; i < 8; i++)
        #pragma unroll
        for (int j = 0; j < 4; j++) dacc[i][j] = 0.f;

    const int hi16 = lane >> 4;
    const int g8 = lane >> 3;
    const int r8 = lane & 7;
    const int arow0 = wm * 32 + (lane & 15);
    const int arow1 = arow0 + 16;

    #pragma unroll 1
    for (int kk = 0; kk < 16; kk++) {
        const int kg = kk * 64;
        __syncthreads();
        #pragma unroll
        for (int j = 0; j < 4; j++) {
            int ch = j * 128 + tid;
            int k = ch >> 3, c = ch & 7;
            const float* src = W + (size_t)(kg + k) * Vn + n0 + c * 8;
            float v[8];
            #pragma unroll
            for (int e = 0; e < 8; e++) {
                int ng = n0 + c * 8 + e;
                v[e] = (ng < Vn) ? src[e] : 0.f;
            }
            uint4 hi4, lo4;
            split8(v, hi4, lo4);
            int off = k * 128 + ((c ^ (k & 7)) << 4);
            *(uint4*)(sm + 16384 + off) = hi4;
            *(uint4*)(sm + 24576 + off) = lo4;
        }
        #pragma unroll
        for (int j = 0; j < 8; j++) {
            int ch = j * 128 + tid;
            int plane = ch >> 9, cc = ch & 511;
            int m = cc >> 3, c = cc & 7;
            cp16(sb + plane * 8192 + m * 128 + ((c ^ (m & 7)) << 4),
                 g_inph + (size_t)plane * APLANE + (size_t)m * 2048 + kg + c * 8);
        }
        CP_COMMIT(); CP_WAIT0();
        __syncthreads();
        #pragma unroll
        for (int seg = 0; seg < 3; seg++) {
            const uint32_t abase = sb + (seg == 2 ? 8192 : 0);
            const uint32_t bbase = sb + 16384 + (seg == 1 ? 8192 : 0);
            #pragma unroll
            for (int kk2 = 0; kk2 < 4; kk2++) {
                uint32_t a0[4], a1[4];
                int ck = kk2 * 2 + hi16;
                LDSM4(a0[0], a0[1], a0[2], a0[3],
                      abase + arow0 * 128 + ((ck ^ (arow0 & 7)) << 4));
                LDSM4(a1[0], a1[1], a1[2], a1[3],
                      abase + arow1 * 128 + ((ck ^ (arow1 & 7)) << 4));
                int kloc = kk2 * 16 + (g8 & 1) * 8 + r8;
                #pragma unroll
                for (int bt = 0; bt < 2; bt++) {
                    int nchunk = wn * 4 + bt * 2 + (g8 >> 1);
                    uint32_t q[4];
                    LDSM4T(q[0], q[1], q[2], q[3],
                           bbase + kloc * 128 + ((nchunk ^ (kloc & 7)) << 4));
                    mma16816(dacc[0 + bt * 2 + 0], a0, q[0], q[1]);
                    mma16816(dacc[0 + bt * 2 + 1], a0, q[2], q[3]);
                    mma16816(dacc[4 + bt * 2 + 0], a1, q[0], q[1]);
                    mma16816(dacc[4 + bt * 2 + 1], a1, q[2], q[3]);
                }
            }
        }
    }
    const int g = lane >> 2;
    const int t = lane & 3;
    #pragma unroll
    for (int at = 0; at < 2; at++)
        #pragma unroll
        for (int bt = 0; bt < 2; bt++)
            #pragma unroll
            for (int h = 0; h < 2; h++) {
                const float* dd = dacc[at * 4 + bt * 2 + h];
                int c0 = n0 + wn * 32 + bt * 16 + h * 8 + 2 * t;
                int r0 = wm * 32 + at * 16 + g;
                if (c0 < Vn) {
                    float bb = db[c0];
                    g_logits[(size_t)r0 * Vn + c0] = dd[0] + bb;
                    g_logits[(size_t)(r0 + 8) * Vn + c0] = dd[2] + bb;
                }
                if (c0 + 1 < Vn) {
                    float bb = db[c0 + 1];
                    g_logits[(size_t)r0 * Vn + c0 + 1] = dd[1] + bb;
                    g_logits[(size_t)(r0 + 8) * Vn + c0 + 1] = dd[3] + bb;
                }
            }
}

// ---------------- softmax over V -> probs ----------------
__global__ void softmax_v_kernel(float* __restrict__ probs) {
    int b = blockIdx.x;
    int tid = threadIdx.x;
    __shared__ float red[1024];
    const float* lg = g_logits + (size_t)b * Vn;
    float m = -1e30f;
    for (int j = tid; j < Vn; j += 1024) m = fmaxf(m, lg[j]);
    red[tid] = m; __syncthreads();
    for (int o = 512; o > 0; o >>= 1) { if (tid < o) red[tid] = fmaxf(red[tid], red[tid + o]); __syncthreads(); }
    m = red[0]; __syncthreads();
    float sum = 0.f;
    float* pb = probs + (size_t)b * Vn;
    for (int j = tid; j < Vn; j += 1024) {
        float e = expf(lg[j] - m);
        pb[j] = e;
        sum += e;
    }
    red[tid] = sum; __syncthreads();
    for (int o = 512; o > 0; o >>= 1) { if (tid < o) red[tid] += red[tid + o]; __syncthreads(); }
    float inv = 1.f / red[0];
    for (int j = tid; j < Vn; j += 1024) pb[j] *= inv;
}

// ---------------- launch ----------------
extern "C" void kernel_launch(void* const* d_in, const int* in_sizes, int n_in,
                              void* d_out, int out_size) {
    const float* enc = (const float*)d_in[0];
    const float* dec = (const float*)d_in[1];
    const float* qh  = (const float*)d_in[2];
    const float* W1  = (const float*)d_in[3];
    const float* b1  = (const float*)d_in[4];
    const float* W2  = (const float*)d_in[5];
    const float* b2  = (const float*)d_in[6];
    const float* aV  = (const float*)d_in[7];
    const float* abV = (const float*)d_in[8];
    const float* lW  = (const float*)d_in[9];
    const float* lb  = (const float*)d_in[10];
    const float* dW  = (const float*)d_in[11];
    const float* db  = (const float*)d_in[12];

    float* out   = (float*)d_out;
    float* probs = out;
    float* hs    = out + (size_t)Bn * Vn;
    float* cs    = hs + (size_t)Ln * Bn * Un;
    float* attnw = cs + (size_t)Ln * Bn * Un;

    static const int RES[8] = {0, 0, 1, 1, 1, 1, 1, 0};

    cudaFuncSetAttribute(score_mma_kernel,
                         cudaFuncAttributeMaxDynamicSharedMemorySize, SC_SMEM);

    copy_x_kernel<<<256, 256>>>(dec);
    ench_kernel<<<65536, 256>>>(enc);
    conv_w1_kernel<<<dim3(32, 32), dim3(32, 8)>>>(W1);
    q2_kernel<<<dim3(Bn, 8), 128>>>(qh, W2, b1, b2);
    score_mma_kernel<<<dim3(Sn / 64, Bn), 512, SC_SMEM>>>(aV, abV);
    softmax_s_kernel<<<Bn, 256>>>(attnw);
    ctx_kernel<<<dim3(Bn, 8), 128>>>();

    for (int l = 0; l < Ln; l++) {
        lstm_mma_kernel<<<dim3(48, 8), 128>>>(lW + (size_t)l * 2048 * 4096);
        lstm_act_kernel<<<Bn, 1024>>>(lb + (size_t)l * 4096, hs, cs, l, RES[l]);
    }

    dense_mma_kernel<<<VnP / 64, 128>>>(dW, db);
    softmax_v_kernel<<<Bn, 1024>>>(probs);
}

// round 6
// speedup vs baseline: 4.2638x; 1.0341x over previous
#include <cuda_runtime.h>
#include <cuda_fp16.h>
#include <math.h>
#include <stdint.h>

#define Bn 64
#define Sn 2048
#define Un 1024
#define Vn 50257
#define VnP 50304
#define Ln 8

// ---------------- scratch (device globals; no allocs allowed) ----------------
__device__ float g_q2[Bn * Un];
__device__ float g_q2p[8][Bn][Un];                     // q2 k-split partials
__device__ float g_score[Bn * Sn];
__device__ float g_attnw[Bn * Sn];
__device__ float g_x[Bn * Un];
__device__ float g_zp8[8 * Bn * 3072];                 // lstm k-split partials (i|g|o)
__device__ float g_logits[(size_t)Bn * Vn];
__device__ __half g_W1h[(size_t)Un * Un];              // W1^T [n][k] fp16
__device__ __half g_ench[(size_t)Bn * Sn * Un];        // enc as fp16
__device__ __half g_inph[2 * Bn * 2048];               // [plane][b][x|ctx] hi/lo

#define APLANE ((size_t)Bn * 2048)

// ======================= helpers =======================
__device__ __forceinline__ uint32_t smem_u32(const void* p) {
    uint32_t a;
    asm("{ .reg .u64 t; cvta.to.shared.u64 t, %1; cvt.u32.u64 %0, t; }" : "=r"(a) : "l"(p));
    return a;
}
__device__ __forceinline__ float tanh_fast(float x) {
    float y;
    asm("tanh.approx.f32 %0, %1;" : "=f"(y) : "f"(x));
    return y;
}
#define LDSM4(r0, r1, r2, r3, addr) \
    asm volatile("ldmatrix.sync.aligned.m8n8.x4.shared.b16 {%0,%1,%2,%3}, [%4];" \
                 : "=r"(r0), "=r"(r1), "=r"(r2), "=r"(r3) : "r"(addr))
#define LDSM4T(r0, r1, r2, r3, addr) \
    asm volatile("ldmatrix.sync.aligned.m8n8.x4.trans.shared.b16 {%0,%1,%2,%3}, [%4];" \
                 : "=r"(r0), "=r"(r1), "=r"(r2), "=r"(r3) : "r"(addr))
__device__ __forceinline__ void mma16816(float* d, const uint32_t* a, uint32_t b0, uint32_t b1) {
    asm volatile(
        "mma.sync.aligned.m16n8k16.row.col.f32.f16.f16.f32 "
        "{%0,%1,%2,%3}, {%4,%5,%6,%7}, {%8,%9}, {%0,%1,%2,%3};"
        : "+f"(d[0]), "+f"(d[1]), "+f"(d[2]), "+f"(d[3])
        : "r"(a[0]), "r"(a[1]), "r"(a[2]), "r"(a[3]), "r"(b0), "r"(b1));
}
__device__ __forceinline__ void cp16(uint32_t s, const void* g) {
    asm volatile("cp.async.ca.shared.global [%0], [%1], 16;" :: "r"(s), "l"(g));
}
#define CP_COMMIT() asm volatile("cp.async.commit_group;" ::: "memory")
#define CP_WAIT1() asm volatile("cp.async.wait_group 1;" ::: "memory")
#define CP_WAIT0() asm volatile("cp.async.wait_group 0;" ::: "memory")

// pack 8 floats -> hi uint4 and lo uint4 (lo = v - hi)
__device__ __forceinline__ void split8(const float* v, uint4& hi4, uint4& lo4) {
    __half2 h[4], l[4];
    #pragma unroll
    for (int i = 0; i < 4; i++) {
        h[i] = __floats2half2_rn(v[2 * i], v[2 * i + 1]);
        float2 hf = __half22float2(h[i]);
        l[i] = __floats2half2_rn(v[2 * i] - hf.x, v[2 * i + 1] - hf.y);
    }
    hi4.x = *reinterpret_cast<uint32_t*>(&h[0]);
    hi4.y = *reinterpret_cast<uint32_t*>(&h[1]);
    hi4.z = *reinterpret_cast<uint32_t*>(&h[2]);
    hi4.w = *reinterpret_cast<uint32_t*>(&h[3]);
    lo4.x = *reinterpret_cast<uint32_t*>(&l[0]);
    lo4.y = *reinterpret_cast<uint32_t*>(&l[1]);
    lo4.z = *reinterpret_cast<uint32_t*>(&l[2]);
    lo4.w = *reinterpret_cast<uint32_t*>(&l[3]);
}

// ---------------- init x = dec_input[:,0,:] ----------------
__global__ void copy_x_kernel(const float* __restrict__ dec) {
    int i = blockIdx.x * 256 + threadIdx.x;
    float v = dec[i];
    g_x[i] = v;
    int b = i >> 10, u = i & 1023;
    __half hi = __float2half_rn(v);
    g_inph[b * 2048 + u] = hi;
    g_inph[APLANE + b * 2048 + u] = __float2half_rn(v - __half2float(hi));
}

// ---------------- enc fp32 -> fp16 streaming ----------------
__global__ void ench_kernel(const float* __restrict__ enc) {
    size_t i = ((size_t)blockIdx.x * 256 + threadIdx.x) * 8;
    float4 v0 = *(const float4*)(enc + i);
    float4 v1 = *(const float4*)(enc + i + 4);
    __half2 h0 = __floats2half2_rn(v0.x, v0.y);
    __half2 h1 = __floats2half2_rn(v0.z, v0.w);
    __half2 h2 = __floats2half2_rn(v1.x, v1.y);
    __half2 h3 = __floats2half2_rn(v1.z, v1.w);
    uint4 u;
    u.x = *reinterpret_cast<uint32_t*>(&h0);
    u.y = *reinterpret_cast<uint32_t*>(&h1);
    u.z = *reinterpret_cast<uint32_t*>(&h2);
    u.w = *reinterpret_cast<uint32_t*>(&h3);
    *reinterpret_cast<uint4*>(g_ench + i) = u;
}

// ---------------- convert W1[k][n] -> g_W1h[n][k] fp16 ----------------
__global__ void conv_w1_kernel(const float* __restrict__ W1) {
    __shared__ float t[32][33];
    int n0 = blockIdx.x * 32, k0 = blockIdx.y * 32;
    int x = threadIdx.x, y = threadIdx.y;
    #pragma unroll
    for (int i = 0; i < 32; i += 8)
        t[y + i][x] = W1[(size_t)(k0 + y + i) * Un + n0 + x];
    __syncthreads();
    #pragma unroll
    for (int i = 0; i < 32; i += 8)
        g_W1h[(size_t)(n0 + y + i) * Un + k0 + x] = __float2half_rn(t[x][y + i]);
}

// ---------------- q2: k-split GEMM, partials -> g_q2p ----------------
__global__ __launch_bounds__(256) void q2_split_kernel(const float* __restrict__ qh,
                                                       const float* __restrict__ W2) {
    __shared__ float qs[128][68];   // [k][b], padded (16B aligned rows)
    const int tid = threadIdx.x;
    const int vt = blockIdx.x;      // 8 v-tiles of 128
    const int ks = blockIdx.y;      // 8 k-splits of 128
    const int v = vt * 128 + (tid & 127);
    const int half = tid >> 7;      // b-range half*32..+32
    const int k0 = ks * 128;

    for (int i = tid; i < 64 * 128; i += 256) {
        int b = i >> 7, k = i & 127;
        qs[k][b] = qh[b * Un + k0 + k];
    }
    __syncthreads();

    float acc[32];
    #pragma unroll
    for (int j = 0; j < 32; j++) acc[j] = 0.f;

    #pragma unroll 1
    for (int k = 0; k < 128; k++) {
        float w = W2[(size_t)(k0 + k) * Un + v];
        const float4* qrow = (const float4*)&qs[k][half * 32];
        #pragma unroll
        for (int j4 = 0; j4 < 8; j4++) {
            float4 q = qrow[j4];
            acc[j4 * 4 + 0] += w * q.x;
            acc[j4 * 4 + 1] += w * q.y;
            acc[j4 * 4 + 2] += w * q.z;
            acc[j4 * 4 + 3] += w * q.w;
        }
    }
    #pragma unroll
    for (int j = 0; j < 32; j++)
        g_q2p[ks][half * 32 + j][v] = acc[j];
}

__global__ void q2_fin_kernel(const float* __restrict__ b1, const float* __restrict__ b2) {
    int i = blockIdx.x * 256 + threadIdx.x;   // 65536
    int b = i >> 10, v = i & 1023;
    float s = b1[v] + b2[v];
    #pragma unroll
    for (int ks = 0; ks < 8; ks++) s += g_q2p[ks][b][v];
    g_q2[i] = s;
}

// =================== HMMA fused score GEMM (512 threads, 16 warps) ===================
#define SCOFF_A 0           // 64 x 2048B = 131072
#define SCOFF_B 131072      // 2 x 32768 (256n x 128B)
#define SCOFF_Q2 196608
#define SCOFF_AV 200704
#define SCOFF_RED 204800    // 256 floats
#define SC_SMEM 205824

__global__ __launch_bounds__(512, 1)
void score_mma_kernel(const float* __restrict__ attnV, const float* __restrict__ attnbV) {
    extern __shared__ char smem[];
    const uint32_t sb = smem_u32(smem);
    const int tid = threadIdx.x;
    const int lane = tid & 31;
    const int wid = tid >> 5;
    const int wm = wid & 3;      // rows wm*16..+16
    const int wn = wid >> 2;     // cols wn*64..+64 of 256-tile
    const int b = blockIdx.y;
    const int s0 = blockIdx.x * 64;

    float* q2s = (float*)(smem + SCOFF_Q2);
    float* avs = (float*)(smem + SCOFF_AV);
    float* red = (float*)(smem + SCOFF_RED);

    for (int i = tid; i < Un; i += 512) {
        q2s[i] = g_q2[b * Un + i];
        avs[i] = attnV[i];
    }

    // A panel: 64x1024 fp16 via cp.async w/ swizzle
    const __half* panel = g_ench + ((size_t)b * Sn + s0) * Un;
    #pragma unroll
    for (int it = 0; it < 16; it++) {
        int id = it * 512 + tid;
        int r = id >> 7;
        int c = id & 127;
        cp16(sb + SCOFF_A + r * 2048 + ((c ^ (r & 7)) << 4),
             panel + (size_t)id * 8);
    }

    auto loadB = [&](int nt, int kk, int buf) {
        #pragma unroll
        for (int h = 0; h < 4; h++) {
            int ch = h * 512 + tid;
            int n = ch >> 3;
            int ck = ch & 7;
            cp16(sb + SCOFF_B + buf * 32768 + n * 128 + ((ck ^ (n & 7)) << 4),
                 g_W1h + (size_t)(nt * 256 + n) * Un + kk * 64 + ck * 8);
        }
    };

    const int ahi = lane >> 4;
    const int arow = wm * 16 + (lane & 15);
    const uint32_t abase = sb + SCOFF_A + arow * 2048;
    const int axr = arow & 7;

    const int bhi = lane >> 4;
    uint32_t bno[4];
    int bxr[4];
    #pragma unroll
    for (int bt = 0; bt < 4; bt++) {
        int bn = wn * 64 + bt * 16 + (lane & 15);
        bno[bt] = bn * 128;
        bxr[bt] = bn & 7;
    }

    const int g = lane >> 2;
    const int t = lane & 3;
    float p0 = 0.f, p1 = 0.f;

    #pragma unroll 1
    for (int nt = 0; nt < 4; nt++) {
        float dacc[8][4];
        #pragma unroll
        for (int i = 0; i < 8; i++)
            #pragma unroll
            for (int j = 0; j < 4; j++) dacc[i][j] = 0.f;

        loadB(nt, 0, 0);
        CP_COMMIT();

        #pragma unroll 1
        for (int kk = 0; kk < 16; kk++) {
            if (kk < 15) {
                loadB(nt, kk + 1, (kk + 1) & 1);
                CP_COMMIT();
                CP_WAIT1();
            } else {
                CP_WAIT0();
            }
            __syncthreads();
            const uint32_t bst = sb + SCOFF_B + (kk & 1) * 32768;
            #pragma unroll
            for (int kk2 = 0; kk2 < 4; kk2++) {
                const int K16 = kk * 4 + kk2;
                uint32_t a[4];
                LDSM4(a[0], a[1], a[2], a[3], abase + (((K16 * 2 + ahi) ^ axr) << 4));
                const int ck = kk2 * 2 + bhi;
                #pragma unroll
                for (int bt = 0; bt < 4; bt++) {
                    uint32_t q[4];
                    LDSM4(q[0], q[1], q[2], q[3], bst + bno[bt] + ((ck ^ bxr[bt]) << 4));
                    mma16816(dacc[bt * 2 + 0], a, q[0], q[2]);
                    mma16816(dacc[bt * 2 + 1], a, q[1], q[3]);
                }
            }
            __syncthreads();
        }
        #pragma unroll
        for (int bt = 0; bt < 4; bt++)
            #pragma unroll
            for (int h = 0; h < 2; h++) {
                const float* dd = dacc[bt * 2 + h];
                int c0 = nt * 256 + wn * 64 + bt * 16 + h * 8 + 2 * t;
                float qa = q2s[c0], qb = q2s[c0 + 1];
                float va = avs[c0], vb = avs[c0 + 1];
                p0 += tanh_fast(dd[0] + qa) * va + tanh_fast(dd[1] + qb) * vb;
                p1 += tanh_fast(dd[2] + qa) * va + tanh_fast(dd[3] + qb) * vb;
            }
    }
    p0 += __shfl_xor_sync(0xffffffffu, p0, 1);
    p0 += __shfl_xor_sync(0xffffffffu, p0, 2);
    p1 += __shfl_xor_sync(0xffffffffu, p1, 1);
    p1 += __shfl_xor_sync(0xffffffffu, p1, 2);
    if (t == 0) {
        red[wn * 64 + wm * 16 + g] = p0;
        red[wn * 64 + wm * 16 + 8 + g] = p1;
    }
    __syncthreads();
    if (tid < 64) {
        g_score[b * Sn + s0 + tid] =
            red[tid] + red[64 + tid] + red[128 + tid] + red[192 + tid] + attnbV[0];
    }
}

// ---------------- softmax over S ----------------
__global__ void softmax_s_kernel(float* __restrict__ out_attnw) {
    int b = blockIdx.x;
    int tid = threadIdx.x;
    __shared__ float red[256];
    float m = -1e30f;
    for (int s = tid; s < Sn; s += 256) m = fmaxf(m, g_score[b * Sn + s]);
    red[tid] = m; __syncthreads();
    for (int o = 128; o > 0; o >>= 1) { if (tid < o) red[tid] = fmaxf(red[tid], red[tid + o]); __syncthreads(); }
    m = red[0]; __syncthreads();
    float sum = 0.f;
    for (int s = tid; s < Sn; s += 256) {
        float e = expf(g_score[b * Sn + s] - m);
        g_attnw[b * Sn + s] = e;
        sum += e;
    }
    red[tid] = sum; __syncthreads();
    for (int o = 128; o > 0; o >>= 1) { if (tid < o) red[tid] += red[tid + o]; __syncthreads(); }
    float inv = 1.f / red[0];
    for (int s = tid; s < Sn; s += 256) {
        float w = g_attnw[b * Sn + s] * inv;
        g_attnw[b * Sn + s] = w;
        out_attnw[b * Sn + s] = w;
    }
}

// ---------------- ctx[b,u] = sum_s attn_w[b,s]*ench[b,s,u]; write fp16 planes ----------------
__global__ void ctx_kernel() {
    int b = blockIdx.x;
    int u = blockIdx.y * 128 + threadIdx.x;
    const __half* e = g_ench + (size_t)b * Sn * Un + u;
    const float* w = g_attnw + b * Sn;
    float a0 = 0.f, a1 = 0.f, a2 = 0.f, a3 = 0.f;
    for (int s = 0; s < Sn; s += 4) {
        a0 += w[s + 0] * __half2float(e[(size_t)(s + 0) * Un]);
        a1 += w[s + 1] * __half2float(e[(size_t)(s + 1) * Un]);
        a2 += w[s + 2] * __half2float(e[(size_t)(s + 2) * Un]);
        a3 += w[s + 3] * __half2float(e[(size_t)(s + 3) * Un]);
    }
    float c = (a0 + a1) + (a2 + a3);
    __half hi = __float2half_rn(c);
    g_inph[b * 2048 + 1024 + u] = hi;
    g_inph[APLANE + b * 2048 + 1024 + u] = __float2half_rn(c - __half2float(hi));
}

// =================== LSTM GEMM: pipelined fused-conversion split-fp16 HMMA ===================
// smem: A stage s @ s*16384 (Ah +0, Al +8192); B stage s @ 32768 + s*16384 (Bh +0, Bl +8192)
__global__ __launch_bounds__(128)
void lstm_mma_kernel(const float* __restrict__ W) {
    __shared__ __align__(128) char sm[65536];
    const uint32_t sb = smem_u32(sm);
    const int tid = threadIdx.x, lane = tid & 31, wid = tid >> 5;
    const int wm = wid & 1, wn = wid >> 1;
    const int nt = blockIdx.x;
    const int ks = blockIdx.y;
    const int k0 = ks * 256;
    const int wcol0 = nt * 64 + (nt >= 16 ? 1024 : 0);
    const int zcol0 = nt * 64;

    float dacc[8][4];
    #pragma unroll
    for (int i = 0; i < 8; i++)
        #pragma unroll
        for (int j = 0; j < 4; j++) dacc[i][j] = 0.f;

    const int hi16 = lane >> 4;
    const int g8 = lane >> 3;
    const int r8 = lane & 7;
    const int arow0 = wm * 32 + (lane & 15);
    const int arow1 = arow0 + 16;

    auto loadW = [&](int kk, float* wv) {
        #pragma unroll
        for (int j = 0; j < 4; j++) {
            int ch = j * 128 + tid;
            int k = ch >> 3, c = ch & 7;
            const float* src = W + (size_t)(k0 + kk * 64 + k) * 4096 + wcol0 + c * 8;
            float4 s0 = *(const float4*)src;
            float4 s1 = *(const float4*)(src + 4);
            wv[j * 8 + 0] = s0.x; wv[j * 8 + 1] = s0.y; wv[j * 8 + 2] = s0.z; wv[j * 8 + 3] = s0.w;
            wv[j * 8 + 4] = s1.x; wv[j * 8 + 5] = s1.y; wv[j * 8 + 6] = s1.z; wv[j * 8 + 7] = s1.w;
        }
    };
    auto stsB = [&](const float* wv, int buf) {
        #pragma unroll
        for (int j = 0; j < 4; j++) {
            int ch = j * 128 + tid;
            int k = ch >> 3, c = ch & 7;
            uint4 hi4, lo4;
            split8(wv + j * 8, hi4, lo4);
            int off = 32768 + buf * 16384 + k * 128 + ((c ^ (k & 7)) << 4);
            *(uint4*)(sm + off) = hi4;
            *(uint4*)(sm + off + 8192) = lo4;
        }
    };
    auto cpA = [&](int kk, int st) {
        #pragma unroll
        for (int j = 0; j < 8; j++) {
            int ch = j * 128 + tid;
            int plane = ch >> 9, cc = ch & 511;
            int m = cc >> 3, c = cc & 7;
            cp16(sb + st * 16384 + plane * 8192 + m * 128 + ((c ^ (m & 7)) << 4),
                 g_inph + (size_t)plane * APLANE + (size_t)m * 2048 + k0 + kk * 64 + c * 8);
        }
    };

    float wv[32], wv2[32];
    loadW(0, wv);
    cpA(0, 0);
    CP_COMMIT();

    #pragma unroll 1
    for (int kk = 0; kk < 4; kk++) {
        const int buf = kk & 1;
        stsB(wv, buf);
        if (kk < 3) loadW(kk + 1, wv2);
        CP_WAIT0();
        __syncthreads();
        if (kk < 3) { cpA(kk + 1, buf ^ 1); CP_COMMIT(); }
        #pragma unroll
        for (int seg = 0; seg < 3; seg++) {
            const uint32_t abase = sb + buf * 16384 + (seg == 2 ? 8192 : 0);
            const uint32_t bbase = sb + 32768 + buf * 16384 + (seg == 1 ? 8192 : 0);
            #pragma unroll
            for (int kk2 = 0; kk2 < 4; kk2++) {
                uint32_t a0[4], a1[4];
                int ck = kk2 * 2 + hi16;
                LDSM4(a0[0], a0[1], a0[2], a0[3],
                      abase + arow0 * 128 + ((ck ^ (arow0 & 7)) << 4));
                LDSM4(a1[0], a1[1], a1[2], a1[3],
                      abase + arow1 * 128 + ((ck ^ (arow1 & 7)) << 4));
                int kloc = kk2 * 16 + (g8 & 1) * 8 + r8;
                #pragma unroll
                for (int bt = 0; bt < 2; bt++) {
                    int nchunk = wn * 4 + bt * 2 + (g8 >> 1);
                    uint32_t q[4];
                    LDSM4T(q[0], q[1], q[2], q[3],
                           bbase + kloc * 128 + ((nchunk ^ (kloc & 7)) << 4));
                    mma16816(dacc[0 + bt * 2 + 0], a0, q[0], q[1]);
                    mma16816(dacc[0 + bt * 2 + 1], a0, q[2], q[3]);
                    mma16816(dacc[4 + bt * 2 + 0], a1, q[0], q[1]);
                    mma16816(dacc[4 + bt * 2 + 1], a1, q[2], q[3]);
                }
            }
        }
        #pragma unroll
        for (int j = 0; j < 32; j++) wv[j] = wv2[j];
        __syncthreads();
    }
    const int g = lane >> 2;
    const int t = lane & 3;
    float* zp = g_zp8 + (size_t)ks * Bn * 3072;
    #pragma unroll
    for (int at = 0; at < 2; at++)
        #pragma unroll
        for (int bt = 0; bt < 2; bt++)
            #pragma unroll
            for (int h = 0; h < 2; h++) {
                const float* dd = dacc[at * 4 + bt * 2 + h];
                int c0 = zcol0 + wn * 32 + bt * 16 + h * 8 + 2 * t;
                int r0 = wm * 32 + at * 16 + g;
                zp[(size_t)r0 * 3072 + c0] = dd[0];
                zp[(size_t)r0 * 3072 + c0 + 1] = dd[1];
                zp[(size_t)(r0 + 8) * 3072 + c0] = dd[2];
                zp[(size_t)(r0 + 8) * 3072 + c0 + 1] = dd[3];
            }
}

// ---------------- LSTM activation ----------------
__global__ void lstm_act_kernel(const float* __restrict__ lb,
                                float* __restrict__ hs, float* __restrict__ cs,
                                int layer, int residual) {
    int b = blockIdx.x;
    int u = threadIdx.x;
    float zi = lb[u], zg = lb[2048 + u], zo = lb[3072 + u];
    #pragma unroll
    for (int ks = 0; ks < 8; ks++) {
        const float* zp = g_zp8 + ((size_t)ks * Bn + b) * 3072;
        zi += zp[u];
        zg += zp[1024 + u];
        zo += zp[2048 + u];
    }
    float c = (1.f / (1.f + expf(-zi))) * tanhf(zg);
    float h = (1.f / (1.f + expf(-zo))) * tanhf(c);
    size_t o = ((size_t)layer * Bn + b) * Un + u;
    hs[o] = h;
    cs[o] = c;
    float xo = g_x[b * Un + u];
    float xn = residual ? (h + xo) : h;
    g_x[b * Un + u] = xn;
    __half hhi = __float2half_rn(xn);
    g_inph[b * 2048 + u] = hhi;
    g_inph[APLANE + b * 2048 + u] = __float2half_rn(xn - __half2float(hhi));
}

// =================== dense GEMM: pipelined fused-conversion split-fp16 HMMA ===================
__global__ __launch_bounds__(128)
void dense_mma_kernel(const float* __restrict__ W, const float* __restrict__ db) {
    __shared__ __align__(128) char sm[65536];
    const uint32_t sb = smem_u32(sm);
    const int tid = threadIdx.x, lane = tid & 31, wid = tid >> 5;
    const int wm = wid & 1, wn = wid >> 1;
    const int n0 = blockIdx.x * 64;

    float dacc[8][4];
    #pragma unroll
    for (int i = 0; i < 8; i++)
        #pragma unroll
        for (int j = 0; j < 4; j++) dacc[i][j] = 0.f;

    const int hi16 = lane >> 4;
    const int g8 = lane >> 3;
    const int r8 = lane & 7;
    const int arow0 = wm * 32 + (lane & 15);
    const int arow1 = arow0 + 16;

    auto loadW = [&](int kk, float* wv) {
        #pragma unroll
        for (int j = 0; j < 4; j++) {
            int ch = j * 128 + tid;
            int k = ch >> 3, c = ch & 7;
            const float* src = W + (size_t)(kk * 64 + k) * Vn + n0 + c * 8;
            #pragma unroll
            for (int e = 0; e < 8; e++) {
                int ng = n0 + c * 8 + e;
                wv[j * 8 + e] = (ng < Vn) ? src[e] : 0.f;
            }
        }
    };
    auto stsB = [&](const float* wv, int buf) {
        #pragma unroll
        for (int j = 0; j < 4; j++) {
            int ch = j * 128 + tid;
            int k = ch >> 3, c = ch & 7;
            uint4 hi4, lo4;
            split8(wv + j * 8, hi4, lo4);
            int off = 32768 + buf * 16384 + k * 128 + ((c ^ (k & 7)) << 4);
            *(uint4*)(sm + off) = hi4;
            *(uint4*)(sm + off + 8192) = lo4;
        }
    };
    auto cpA = [&](int kk, int st) {
        #pragma unroll
        for (int j = 0; j < 8; j++) {
            int ch = j * 128 + tid;
            int plane = ch >> 9, cc = ch & 511;
            int m = cc >> 3, c = cc & 7;
            cp16(sb + st * 16384 + plane * 8192 + m * 128 + ((c ^ (m & 7)) << 4),
                 g_inph + (size_t)plane * APLANE + (size_t)m * 2048 + kk * 64 + c * 8);
        }
    };

    float wv[32], wv2[32];
    loadW(0, wv);
    cpA(0, 0);
    CP_COMMIT();

    #pragma unroll 1
    for (int kk = 0; kk < 16; kk++) {
        const int buf = kk & 1;
        stsB(wv, buf);
        if (kk < 15) loadW(kk + 1, wv2);
        CP_WAIT0();
        __syncthreads();
        if (kk < 15) { cpA(kk + 1, buf ^ 1); CP_COMMIT(); }
        #pragma unroll
        for (int seg = 0; seg < 3; seg++) {
            const uint32_t abase = sb + buf * 16384 + (seg == 2 ? 8192 : 0);
            const uint32_t bbase = sb + 32768 + buf * 16384 + (seg == 1 ? 8192 : 0);
            #pragma unroll
            for (int kk2 = 0; kk2 < 4; kk2++) {
                uint32_t a0[4], a1[4];
                int ck = kk2 * 2 + hi16;
                LDSM4(a0[0], a0[1], a0[2], a0[3],
                      abase + arow0 * 128 + ((ck ^ (arow0 & 7)) << 4));
                LDSM4(a1[0], a1[1], a1[2], a1[3],
                      abase + arow1 * 128 + ((ck ^ (arow1 & 7)) << 4));
                int kloc = kk2 * 16 + (g8 & 1) * 8 + r8;
                #pragma unroll
                for (int bt = 0; bt < 2; bt++) {
                    int nchunk = wn * 4 + bt * 2 + (g8 >> 1);
                    uint32_t q[4];
                    LDSM4T(q[0], q[1], q[2], q[3],
                           bbase + kloc * 128 + ((nchunk ^ (kloc & 7)) << 4));
                    mma16816(dacc[0 + bt * 2 + 0], a0, q[0], q[1]);
                    mma16816(dacc[0 + bt * 2 + 1], a0, q[2], q[3]);
                    mma16816(dacc[4 + bt * 2 + 0], a1, q[0], q[1]);
                    mma16816(dacc[4 + bt * 2 + 1], a1, q[2], q[3]);
                }
            }
        }
        #pragma unroll
        for (int j = 0; j < 32; j++) wv[j] = wv2[j];
        __syncthreads();
    }
    const int g = lane >> 2;
    const int t = lane & 3;
    #pragma unroll
    for (int at = 0; at < 2; at++)
        #pragma unroll
        for (int bt = 0; bt < 2; bt++)
            #pragma unroll
            for (int h = 0; h < 2; h++) {
                const float* dd = dacc[at * 4 + bt * 2 + h];
                int c0 = n0 + wn * 32 + bt * 16 + h * 8 + 2 * t;
                int r0 = wm * 32 + at * 16 + g;
                if (c0 < Vn) {
                    float bb = db[c0];
                    g_logits[(size_t)r0 * Vn + c0] = dd[0] + bb;
                    g_logits[(size_t)(r0 + 8) * Vn + c0] = dd[2] + bb;
                }
                if (c0 + 1 < Vn) {
                    float bb = db[c0 + 1];
                    g_logits[(size_t)r0 * Vn + c0 + 1] = dd[1] + bb;
                    g_logits[(size_t)(r0 + 8) * Vn + c0 + 1] = dd[3] + bb;
                }
            }
}

// ---------------- softmax over V -> probs ----------------
__global__ void softmax_v_kernel(float* __restrict__ probs) {
    int b = blockIdx.x;
    int tid = threadIdx.x;
    __shared__ float red[1024];
    const float* lg = g_logits + (size_t)b * Vn;
    float m = -1e30f;
    for (int j = tid; j < Vn; j += 1024) m = fmaxf(m, lg[j]);
    red[tid] = m; __syncthreads();
    for (int o = 512; o > 0; o >>= 1) { if (tid < o) red[tid] = fmaxf(red[tid], red[tid + o]); __syncthreads(); }
    m = red[0]; __syncthreads();
    float sum = 0.f;
    float* pb = probs + (size_t)b * Vn;
    for (int j = tid; j < Vn; j += 1024) {
        float e = expf(lg[j] - m);
        pb[j] = e;
        sum += e;
    }
    red[tid] = sum; __syncthreads();
    for (int o = 512; o > 0; o >>= 1) { if (tid < o) red[tid] += red[tid + o]; __syncthreads(); }
    float inv = 1.f / red[0];
    for (int j = tid; j < Vn; j += 1024) pb[j] *= inv;
}

// ---------------- launch ----------------
extern "C" void kernel_launch(void* const* d_in, const int* in_sizes, int n_in,
                              void* d_out, int out_size) {
    const float* enc = (const float*)d_in[0];
    const float* dec = (const float*)d_in[1];
    const float* qh  = (const float*)d_in[2];
    const float* W1  = (const float*)d_in[3];
    const float* b1  = (const float*)d_in[4];
    const float* W2  = (const float*)d_in[5];
    const float* b2  = (const float*)d_in[6];
    const float* aV  = (const float*)d_in[7];
    const float* abV = (const float*)d_in[8];
    const float* lW  = (const float*)d_in[9];
    const float* lb  = (const float*)d_in[10];
    const float* dW  = (const float*)d_in[11];
    const float* db  = (const float*)d_in[12];

    float* out   = (float*)d_out;
    float* probs = out;
    float* hs    = out + (size_t)Bn * Vn;
    float* cs    = hs + (size_t)Ln * Bn * Un;
    float* attnw = cs + (size_t)Ln * Bn * Un;

    static const int RES[8] = {0, 0, 1, 1, 1, 1, 1, 0};

    cudaFuncSetAttribute(score_mma_kernel,
                         cudaFuncAttributeMaxDynamicSharedMemorySize, SC_SMEM);

    copy_x_kernel<<<256, 256>>>(dec);
    ench_kernel<<<65536, 256>>>(enc);
    conv_w1_kernel<<<dim3(32, 32), dim3(32, 8)>>>(W1);
    q2_split_kernel<<<dim3(8, 8), 256>>>(qh, W2);
    q2_fin_kernel<<<256, 256>>>(b1, b2);
    score_mma_kernel<<<dim3(Sn / 64, Bn), 512, SC_SMEM>>>(aV, abV);
    softmax_s_kernel<<<Bn, 256>>>(attnw);
    ctx_kernel<<<dim3(Bn, 8), 128>>>();

    for (int l = 0; l < Ln; l++) {
        lstm_mma_kernel<<<dim3(48, 8), 128>>>(lW + (size_t)l * 2048 * 4096);
        lstm_act_kernel<<<Bn, 1024>>>(lb + (size_t)l * 4096, hs, cs, l, RES[l]);
    }

    dense_mma_kernel<<<VnP / 64, 128>>>(dW, db);
    softmax_v_kernel<<<Bn, 1024>>>(probs);
}

// round 7
// speedup vs baseline: 4.8711x; 1.1424x over previous
#include <cuda_runtime.h>
#include <cuda_fp16.h>
#include <math.h>
#include <stdint.h>

#define Bn 64
#define Sn 2048
#define Un 1024
#define Vn 50257
#define VnP 50304
#define Ln 8

// ---------------- scratch (device globals; no allocs allowed) ----------------
__device__ float g_q2[Bn * Un];
__device__ float g_q2p[32][Bn][Un];                    // q2 k-split partials
__device__ float g_ctxp[8][Bn][Un];                    // ctx s-split partials
__device__ float g_score[Bn * Sn];
__device__ float g_attnw[Bn * Sn];
__device__ float g_x[Bn * Un];
__device__ float g_zp8[8 * Bn * 3072];                 // lstm k-split partials (i|g|o)
__device__ float g_logits[(size_t)Bn * Vn];
__device__ __half g_W1h[(size_t)Un * Un];              // W1^T [n][k] fp16
__device__ __half g_ench[(size_t)Bn * Sn * Un];        // enc as fp16
__device__ __half g_inph[2 * Bn * 2048];               // [plane][b][x|ctx] hi/lo

#define APLANE ((size_t)Bn * 2048)

// ======================= helpers =======================
__device__ __forceinline__ uint32_t smem_u32(const void* p) {
    uint32_t a;
    asm("{ .reg .u64 t; cvta.to.shared.u64 t, %1; cvt.u32.u64 %0, t; }" : "=r"(a) : "l"(p));
    return a;
}
__device__ __forceinline__ float tanh_fast(float x) {
    float y;
    asm("tanh.approx.f32 %0, %1;" : "=f"(y) : "f"(x));
    return y;
}
#define LDSM4(r0, r1, r2, r3, addr) \
    asm volatile("ldmatrix.sync.aligned.m8n8.x4.shared.b16 {%0,%1,%2,%3}, [%4];" \
                 : "=r"(r0), "=r"(r1), "=r"(r2), "=r"(r3) : "r"(addr))
#define LDSM4T(r0, r1, r2, r3, addr) \
    asm volatile("ldmatrix.sync.aligned.m8n8.x4.trans.shared.b16 {%0,%1,%2,%3}, [%4];" \
                 : "=r"(r0), "=r"(r1), "=r"(r2), "=r"(r3) : "r"(addr))
__device__ __forceinline__ void mma16816(float* d, const uint32_t* a, uint32_t b0, uint32_t b1) {
    asm volatile(
        "mma.sync.aligned.m16n8k16.row.col.f32.f16.f16.f32 "
        "{%0,%1,%2,%3}, {%4,%5,%6,%7}, {%8,%9}, {%0,%1,%2,%3};"
        : "+f"(d[0]), "+f"(d[1]), "+f"(d[2]), "+f"(d[3])
        : "r"(a[0]), "r"(a[1]), "r"(a[2]), "r"(a[3]), "r"(b0), "r"(b1));
}
__device__ __forceinline__ void cp16(uint32_t s, const void* g) {
    asm volatile("cp.async.ca.shared.global [%0], [%1], 16;" :: "r"(s), "l"(g));
}
#define CP_COMMIT() asm volatile("cp.async.commit_group;" ::: "memory")
#define CP_WAIT1() asm volatile("cp.async.wait_group 1;" ::: "memory")
#define CP_WAIT0() asm volatile("cp.async.wait_group 0;" ::: "memory")

// pack 8 floats -> hi uint4 and lo uint4 (lo = v - hi)
__device__ __forceinline__ void split8(const float* v, uint4& hi4, uint4& lo4) {
    __half2 h[4], l[4];
    #pragma unroll
    for (int i = 0; i < 4; i++) {
        h[i] = __floats2half2_rn(v[2 * i], v[2 * i + 1]);
        float2 hf = __half22float2(h[i]);
        l[i] = __floats2half2_rn(v[2 * i] - hf.x, v[2 * i + 1] - hf.y);
    }
    hi4.x = *reinterpret_cast<uint32_t*>(&h[0]);
    hi4.y = *reinterpret_cast<uint32_t*>(&h[1]);
    hi4.z = *reinterpret_cast<uint32_t*>(&h[2]);
    hi4.w = *reinterpret_cast<uint32_t*>(&h[3]);
    lo4.x = *reinterpret_cast<uint32_t*>(&l[0]);
    lo4.y = *reinterpret_cast<uint32_t*>(&l[1]);
    lo4.z = *reinterpret_cast<uint32_t*>(&l[2]);
    lo4.w = *reinterpret_cast<uint32_t*>(&l[3]);
}

// ---------------- init x = dec_input[:,0,:] ----------------
__global__ void copy_x_kernel(const float* __restrict__ dec) {
    int i = blockIdx.x * 256 + threadIdx.x;
    float v = dec[i];
    g_x[i] = v;
    int b = i >> 10, u = i & 1023;
    __half hi = __float2half_rn(v);
    g_inph[b * 2048 + u] = hi;
    g_inph[APLANE + b * 2048 + u] = __float2half_rn(v - __half2float(hi));
}

// ---------------- enc fp32 -> fp16 streaming ----------------
__global__ void ench_kernel(const float* __restrict__ enc) {
    size_t i = ((size_t)blockIdx.x * 256 + threadIdx.x) * 8;
    float4 v0 = *(const float4*)(enc + i);
    float4 v1 = *(const float4*)(enc + i + 4);
    __half2 h0 = __floats2half2_rn(v0.x, v0.y);
    __half2 h1 = __floats2half2_rn(v0.z, v0.w);
    __half2 h2 = __floats2half2_rn(v1.x, v1.y);
    __half2 h3 = __floats2half2_rn(v1.z, v1.w);
    uint4 u;
    u.x = *reinterpret_cast<uint32_t*>(&h0);
    u.y = *reinterpret_cast<uint32_t*>(&h1);
    u.z = *reinterpret_cast<uint32_t*>(&h2);
    u.w = *reinterpret_cast<uint32_t*>(&h3);
    *reinterpret_cast<uint4*>(g_ench + i) = u;
}

// ---------------- convert W1[k][n] -> g_W1h[n][k] fp16 ----------------
__global__ void conv_w1_kernel(const float* __restrict__ W1) {
    __shared__ float t[32][33];
    int n0 = blockIdx.x * 32, k0 = blockIdx.y * 32;
    int x = threadIdx.x, y = threadIdx.y;
    #pragma unroll
    for (int i = 0; i < 32; i += 8)
        t[y + i][x] = W1[(size_t)(k0 + y + i) * Un + n0 + x];
    __syncthreads();
    #pragma unroll
    for (int i = 0; i < 32; i += 8)
        g_W1h[(size_t)(n0 + y + i) * Un + k0 + x] = __float2half_rn(t[x][y + i]);
}

// ---------------- q2: 32-way k-split GEMM ----------------
__global__ __launch_bounds__(256) void q2_split_kernel(const float* __restrict__ qh,
                                                       const float* __restrict__ W2) {
    __shared__ float qs[32][68];    // [k][b], padded
    const int tid = threadIdx.x;
    const int vt = blockIdx.x;      // 8 v-tiles of 128
    const int ks = blockIdx.y;      // 32 k-splits of 32
    const int v = vt * 128 + (tid & 127);
    const int half = tid >> 7;      // b-range half*32..+32
    const int k0 = ks * 32;

    for (int i = tid; i < 64 * 32; i += 256) {
        int b = i >> 5, k = i & 31;
        qs[k][b] = qh[b * Un + k0 + k];
    }
    __syncthreads();

    float acc[32];
    #pragma unroll
    for (int j = 0; j < 32; j++) acc[j] = 0.f;

    #pragma unroll 1
    for (int k = 0; k < 32; k++) {
        float w = W2[(size_t)(k0 + k) * Un + v];
        const float4* qrow = (const float4*)&qs[k][half * 32];
        #pragma unroll
        for (int j4 = 0; j4 < 8; j4++) {
            float4 q = qrow[j4];
            acc[j4 * 4 + 0] += w * q.x;
            acc[j4 * 4 + 1] += w * q.y;
            acc[j4 * 4 + 2] += w * q.z;
            acc[j4 * 4 + 3] += w * q.w;
        }
    }
    #pragma unroll
    for (int j = 0; j < 32; j++)
        g_q2p[ks][half * 32 + j][v] = acc[j];
}

__global__ void q2_fin_kernel(const float* __restrict__ b1, const float* __restrict__ b2) {
    int i = blockIdx.x * 256 + threadIdx.x;   // 65536
    int b = i >> 10, v = i & 1023;
    float s = b1[v] + b2[v];
    #pragma unroll
    for (int ks = 0; ks < 32; ks++) s += g_q2p[ks][b][v];
    g_q2[i] = s;
}

// =================== HMMA fused score GEMM (256 threads, 2m x 4n warps) ===================
#define SCOFF_A 0           // 64 x 2048B = 131072
#define SCOFF_B 131072      // 2 x 32768 (256n x 128B)
#define SCOFF_Q2 196608
#define SCOFF_AV 200704
#define SCOFF_RED 204800    // 256 floats
#define SC_SMEM 205824

__global__ __launch_bounds__(256, 1)
void score_mma_kernel(const float* __restrict__ attnV, const float* __restrict__ attnbV) {
    extern __shared__ char smem[];
    const uint32_t sb = smem_u32(smem);
    const int tid = threadIdx.x;
    const int lane = tid & 31;
    const int wid = tid >> 5;
    const int wm = wid & 1;      // rows wm*32..+32
    const int wn = wid >> 1;     // cols wn*64..+64 of 256-tile
    const int b = blockIdx.y;
    const int s0 = blockIdx.x * 64;

    float* q2s = (float*)(smem + SCOFF_Q2);
    float* avs = (float*)(smem + SCOFF_AV);
    float* red = (float*)(smem + SCOFF_RED);

    for (int i = tid; i < Un; i += 256) {
        q2s[i] = g_q2[b * Un + i];
        avs[i] = attnV[i];
    }

    // A panel: 64x1024 fp16 via cp.async w/ swizzle (8192 chunks, 32/thread)
    const __half* panel = g_ench + ((size_t)b * Sn + s0) * Un;
    #pragma unroll
    for (int it = 0; it < 32; it++) {
        int id = it * 256 + tid;
        int r = id >> 7;
        int c = id & 127;
        cp16(sb + SCOFF_A + r * 2048 + ((c ^ (r & 7)) << 4),
             panel + (size_t)id * 8);
    }

    auto loadB = [&](int nt, int kk, int buf) {
        #pragma unroll
        for (int h = 0; h < 8; h++) {
            int ch = h * 256 + tid;
            int n = ch >> 3;
            int ck = ch & 7;
            cp16(sb + SCOFF_B + buf * 32768 + n * 128 + ((ck ^ (n & 7)) << 4),
                 g_W1h + (size_t)(nt * 256 + n) * Un + kk * 64 + ck * 8);
        }
    };

    // A ldsm bases: two 16-row tiles per warp
    const int ahi = lane >> 4;
    const int arow0 = wm * 32 + (lane & 15);
    const int arow1 = arow0 + 16;
    const uint32_t ab0 = sb + SCOFF_A + arow0 * 2048;
    const uint32_t ab1 = sb + SCOFF_A + arow1 * 2048;
    const int ax0 = arow0 & 7, ax1 = arow1 & 7;

    // B ldsm bases (4 col-tiles of 16)
    const int bhi = lane >> 4;
    uint32_t bno[4];
    int bxr[4];
    #pragma unroll
    for (int bt = 0; bt < 4; bt++) {
        int bn = wn * 64 + bt * 16 + (lane & 15);
        bno[bt] = bn * 128;
        bxr[bt] = bn & 7;
    }

    const int g = lane >> 2;
    const int t = lane & 3;
    float pa[4];
    #pragma unroll
    for (int i = 0; i < 4; i++) pa[i] = 0.f;

    #pragma unroll 1
    for (int nt = 0; nt < 4; nt++) {
        float dacc[16][4];
        #pragma unroll
        for (int i = 0; i < 16; i++)
            #pragma unroll
            for (int j = 0; j < 4; j++) dacc[i][j] = 0.f;

        loadB(nt, 0, 0);
        CP_COMMIT();

        #pragma unroll 1
        for (int kk = 0; kk < 16; kk++) {
            if (kk < 15) {
                loadB(nt, kk + 1, (kk + 1) & 1);
                CP_COMMIT();
                CP_WAIT1();
            } else {
                CP_WAIT0();
            }
            __syncthreads();
            const uint32_t bst = sb + SCOFF_B + (kk & 1) * 32768;
            #pragma unroll
            for (int kk2 = 0; kk2 < 4; kk2++) {
                const int K16 = kk * 4 + kk2;
                uint32_t a0[4], a1[4];
                LDSM4(a0[0], a0[1], a0[2], a0[3], ab0 + (((K16 * 2 + ahi) ^ ax0) << 4));
                LDSM4(a1[0], a1[1], a1[2], a1[3], ab1 + (((K16 * 2 + ahi) ^ ax1) << 4));
                const int ck = kk2 * 2 + bhi;
                #pragma unroll
                for (int bt = 0; bt < 4; bt++) {
                    uint32_t q[4];
                    LDSM4(q[0], q[1], q[2], q[3], bst + bno[bt] + ((ck ^ bxr[bt]) << 4));
                    mma16816(dacc[0 + bt * 2 + 0], a0, q[0], q[2]);
                    mma16816(dacc[0 + bt * 2 + 1], a0, q[1], q[3]);
                    mma16816(dacc[8 + bt * 2 + 0], a1, q[0], q[2]);
                    mma16816(dacc[8 + bt * 2 + 1], a1, q[1], q[3]);
                }
            }
            __syncthreads();
        }
        // epilogue: tanh(D + q2) * attnV
        #pragma unroll
        for (int at = 0; at < 2; at++)
            #pragma unroll
            for (int bt = 0; bt < 4; bt++)
                #pragma unroll
                for (int h = 0; h < 2; h++) {
                    const float* dd = dacc[at * 8 + bt * 2 + h];
                    int c0 = nt * 256 + wn * 64 + bt * 16 + h * 8 + 2 * t;
                    float qa = q2s[c0], qb = q2s[c0 + 1];
                    float va = avs[c0], vb = avs[c0 + 1];
                    pa[at * 2 + 0] += tanh_fast(dd[0] + qa) * va + tanh_fast(dd[1] + qb) * vb;
                    pa[at * 2 + 1] += tanh_fast(dd[2] + qa) * va + tanh_fast(dd[3] + qb) * vb;
                }
    }
    #pragma unroll
    for (int i = 0; i < 4; i++) {
        pa[i] += __shfl_xor_sync(0xffffffffu, pa[i], 1);
        pa[i] += __shfl_xor_sync(0xffffffffu, pa[i], 2);
    }
    if (t == 0) {
        #pragma unroll
        for (int at = 0; at < 2; at++)
            #pragma unroll
            for (int hh = 0; hh < 2; hh++)
                red[wn * 64 + wm * 32 + at * 16 + hh * 8 + g] = pa[at * 2 + hh];
    }
    __syncthreads();
    if (tid < 64) {
        g_score[b * Sn + s0 + tid] =
            red[tid] + red[64 + tid] + red[128 + tid] + red[192 + tid] + attnbV[0];
    }
}

// ---------------- softmax over S ----------------
__global__ void softmax_s_kernel(float* __restrict__ out_attnw) {
    int b = blockIdx.x;
    int tid = threadIdx.x;
    __shared__ float red[256];
    float m = -1e30f;
    for (int s = tid; s < Sn; s += 256) m = fmaxf(m, g_score[b * Sn + s]);
    red[tid] = m; __syncthreads();
    for (int o = 128; o > 0; o >>= 1) { if (tid < o) red[tid] = fmaxf(red[tid], red[tid + o]); __syncthreads(); }
    m = red[0]; __syncthreads();
    float sum = 0.f;
    for (int s = tid; s < Sn; s += 256) {
        float e = expf(g_score[b * Sn + s] - m);
        g_attnw[b * Sn + s] = e;
        sum += e;
    }
    red[tid] = sum; __syncthreads();
    for (int o = 128; o > 0; o >>= 1) { if (tid < o) red[tid] += red[tid + o]; __syncthreads(); }
    float inv = 1.f / red[0];
    for (int s = tid; s < Sn; s += 256) {
        float w = g_attnw[b * Sn + s] * inv;
        g_attnw[b * Sn + s] = w;
        out_attnw[b * Sn + s] = w;
    }
}

// ---------------- ctx partials: 8 s-splits, half2 loads ----------------
__global__ void ctx_part_kernel() {
    int b = blockIdx.x;
    int u0 = (blockIdx.y * 128 + threadIdx.x) * 2;   // blockIdx.y in [0,4)
    int ss = blockIdx.z;                             // [0,8)
    const __half2* e = (const __half2*)(g_ench + (size_t)b * Sn * Un +
                                        (size_t)(ss * 256) * Un + u0);
    const float* w = g_attnw + b * Sn + ss * 256;
    float ax = 0.f, ay = 0.f;
    #pragma unroll 4
    for (int s = 0; s < 256; s++) {
        float2 v = __half22float2(e[(size_t)s * (Un / 2)]);
        float ws = w[s];
        ax += ws * v.x;
        ay += ws * v.y;
    }
    g_ctxp[ss][b][u0] = ax;
    g_ctxp[ss][b][u0 + 1] = ay;
}

__global__ void ctx_fin_kernel() {
    int i = blockIdx.x * 256 + threadIdx.x;   // 65536
    int b = i >> 10, u = i & 1023;
    float c = 0.f;
    #pragma unroll
    for (int ss = 0; ss < 8; ss++) c += g_ctxp[ss][b][u];
    __half hi = __float2half_rn(c);
    g_inph[b * 2048 + 1024 + u] = hi;
    g_inph[APLANE + b * 2048 + 1024 + u] = __float2half_rn(c - __half2float(hi));
}

// =================== LSTM GEMM: pipelined fused-conversion split-fp16 HMMA ===================
__global__ __launch_bounds__(128)
void lstm_mma_kernel(const float* __restrict__ W) {
    __shared__ __align__(128) char sm[65536];
    const uint32_t sb = smem_u32(sm);
    const int tid = threadIdx.x, lane = tid & 31, wid = tid >> 5;
    const int wm = wid & 1, wn = wid >> 1;
    const int nt = blockIdx.x;
    const int ks = blockIdx.y;
    const int k0 = ks * 256;
    const int wcol0 = nt * 64 + (nt >= 16 ? 1024 : 0);
    const int zcol0 = nt * 64;

    float dacc[8][4];
    #pragma unroll
    for (int i = 0; i < 8; i++)
        #pragma unroll
        for (int j = 0; j < 4; j++) dacc[i][j] = 0.f;

    const int hi16 = lane >> 4;
    const int g8 = lane >> 3;
    const int r8 = lane & 7;
    const int arow0 = wm * 32 + (lane & 15);
    const int arow1 = arow0 + 16;

    auto loadW = [&](int kk, float* wv) {
        #pragma unroll
        for (int j = 0; j < 4; j++) {
            int ch = j * 128 + tid;
            int k = ch >> 3, c = ch & 7;
            const float* src = W + (size_t)(k0 + kk * 64 + k) * 4096 + wcol0 + c * 8;
            float4 s0 = *(const float4*)src;
            float4 s1 = *(const float4*)(src + 4);
            wv[j * 8 + 0] = s0.x; wv[j * 8 + 1] = s0.y; wv[j * 8 + 2] = s0.z; wv[j * 8 + 3] = s0.w;
            wv[j * 8 + 4] = s1.x; wv[j * 8 + 5] = s1.y; wv[j * 8 + 6] = s1.z; wv[j * 8 + 7] = s1.w;
        }
    };
    auto stsB = [&](const float* wv, int buf) {
        #pragma unroll
        for (int j = 0; j < 4; j++) {
            int ch = j * 128 + tid;
            int k = ch >> 3, c = ch & 7;
            uint4 hi4, lo4;
            split8(wv + j * 8, hi4, lo4);
            int off = 32768 + buf * 16384 + k * 128 + ((c ^ (k & 7)) << 4);
            *(uint4*)(sm + off) = hi4;
            *(uint4*)(sm + off + 8192) = lo4;
        }
    };
    auto cpA = [&](int kk, int st) {
        #pragma unroll
        for (int j = 0; j < 8; j++) {
            int ch = j * 128 + tid;
            int plane = ch >> 9, cc = ch & 511;
            int m = cc >> 3, c = cc & 7;
            cp16(sb + st * 16384 + plane * 8192 + m * 128 + ((c ^ (m & 7)) << 4),
                 g_inph + (size_t)plane * APLANE + (size_t)m * 2048 + k0 + kk * 64 + c * 8);
        }
    };

    float wv[32], wv2[32];
    loadW(0, wv);
    cpA(0, 0);
    CP_COMMIT();

    #pragma unroll 1
    for (int kk = 0; kk < 4; kk++) {
        const int buf = kk & 1;
        stsB(wv, buf);
        if (kk < 3) loadW(kk + 1, wv2);
        CP_WAIT0();
        __syncthreads();
        if (kk < 3) { cpA(kk + 1, buf ^ 1); CP_COMMIT(); }
        #pragma unroll
        for (int seg = 0; seg < 3; seg++) {
            const uint32_t abase = sb + buf * 16384 + (seg == 2 ? 8192 : 0);
            const uint32_t bbase = sb + 32768 + buf * 16384 + (seg == 1 ? 8192 : 0);
            #pragma unroll
            for (int kk2 = 0; kk2 < 4; kk2++) {
                uint32_t a0[4], a1[4];
                int ck = kk2 * 2 + hi16;
                LDSM4(a0[0], a0[1], a0[2], a0[3],
                      abase + arow0 * 128 + ((ck ^ (arow0 & 7)) << 4));
                LDSM4(a1[0], a1[1], a1[2], a1[3],
                      abase + arow1 * 128 + ((ck ^ (arow1 & 7)) << 4));
                int kloc = kk2 * 16 + (g8 & 1) * 8 + r8;
                #pragma unroll
                for (int bt = 0; bt < 2; bt++) {
                    int nchunk = wn * 4 + bt * 2 + (g8 >> 1);
                    uint32_t q[4];
                    LDSM4T(q[0], q[1], q[2], q[3],
                           bbase + kloc * 128 + ((nchunk ^ (kloc & 7)) << 4));
                    mma16816(dacc[0 + bt * 2 + 0], a0, q[0], q[1]);
                    mma16816(dacc[0 + bt * 2 + 1], a0, q[2], q[3]);
                    mma16816(dacc[4 + bt * 2 + 0], a1, q[0], q[1]);
                    mma16816(dacc[4 + bt * 2 + 1], a1, q[2], q[3]);
                }
            }
        }
        #pragma unroll
        for (int j = 0; j < 32; j++) wv[j] = wv2[j];
        __syncthreads();
    }
    const int g = lane >> 2;
    const int t = lane & 3;
    float* zp = g_zp8 + (size_t)ks * Bn * 3072;
    #pragma unroll
    for (int at = 0; at < 2; at++)
        #pragma unroll
        for (int bt = 0; bt < 2; bt++)
            #pragma unroll
            for (int h = 0; h < 2; h++) {
                const float* dd = dacc[at * 4 + bt * 2 + h];
                int c0 = zcol0 + wn * 32 + bt * 16 + h * 8 + 2 * t;
                int r0 = wm * 32 + at * 16 + g;
                zp[(size_t)r0 * 3072 + c0] = dd[0];
                zp[(size_t)r0 * 3072 + c0 + 1] = dd[1];
                zp[(size_t)(r0 + 8) * 3072 + c0] = dd[2];
                zp[(size_t)(r0 + 8) * 3072 + c0 + 1] = dd[3];
            }
}

// ---------------- LSTM activation ----------------
__global__ void lstm_act_kernel(const float* __restrict__ lb,
                                float* __restrict__ hs, float* __restrict__ cs,
                                int layer, int residual) {
    int b = blockIdx.x;
    int u = threadIdx.x;
    float zi = lb[u], zg = lb[2048 + u], zo = lb[3072 + u];
    #pragma unroll
    for (int ks = 0; ks < 8; ks++) {
        const float* zp = g_zp8 + ((size_t)ks * Bn + b) * 3072;
        zi += zp[u];
        zg += zp[1024 + u];
        zo += zp[2048 + u];
    }
    float c = (1.f / (1.f + expf(-zi))) * tanhf(zg);
    float h = (1.f / (1.f + expf(-zo))) * tanhf(c);
    size_t o = ((size_t)layer * Bn + b) * Un + u;
    hs[o] = h;
    cs[o] = c;
    float xo = g_x[b * Un + u];
    float xn = residual ? (h + xo) : h;
    g_x[b * Un + u] = xn;
    __half hhi = __float2half_rn(xn);
    g_inph[b * 2048 + u] = hhi;
    g_inph[APLANE + b * 2048 + u] = __float2half_rn(xn - __half2float(hhi));
}

// =================== dense GEMM: pipelined fused-conversion split-fp16 HMMA ===================
__global__ __launch_bounds__(128)
void dense_mma_kernel(const float* __restrict__ W, const float* __restrict__ db) {
    __shared__ __align__(128) char sm[65536];
    const uint32_t sb = smem_u32(sm);
    const int tid = threadIdx.x, lane = tid & 31, wid = tid >> 5;
    const int wm = wid & 1, wn = wid >> 1;
    const int n0 = blockIdx.x * 64;

    float dacc[8][4];
    #pragma unroll
    for (int i = 0; i < 8; i++)
        #pragma unroll
        for (int j = 0; j < 4; j++) dacc[i][j] = 0.f;

    const int hi16 = lane >> 4;
    const int g8 = lane >> 3;
    const int r8 = lane & 7;
    const int arow0 = wm * 32 + (lane & 15);
    const int arow1 = arow0 + 16;

    auto loadW = [&](int kk, float* wv) {
        #pragma unroll
        for (int j = 0; j < 4; j++) {
            int ch = j * 128 + tid;
            int k = ch >> 3, c = ch & 7;
            const float* src = W + (size_t)(kk * 64 + k) * Vn + n0 + c * 8;
            #pragma unroll
            for (int e = 0; e < 8; e++) {
                int ng = n0 + c * 8 + e;
                wv[j * 8 + e] = (ng < Vn) ? src[e] : 0.f;
            }
        }
    };
    auto stsB = [&](const float* wv, int buf) {
        #pragma unroll
        for (int j = 0; j < 4; j++) {
            int ch = j * 128 + tid;
            int k = ch >> 3, c = ch & 7;
            uint4 hi4, lo4;
            split8(wv + j * 8, hi4, lo4);
            int off = 32768 + buf * 16384 + k * 128 + ((c ^ (k & 7)) << 4);
            *(uint4*)(sm + off) = hi4;
            *(uint4*)(sm + off + 8192) = lo4;
        }
    };
    auto cpA = [&](int kk, int st) {
        #pragma unroll
        for (int j = 0; j < 8; j++) {
            int ch = j * 128 + tid;
            int plane = ch >> 9, cc = ch & 511;
            int m = cc >> 3, c = cc & 7;
            cp16(sb + st * 16384 + plane * 8192 + m * 128 + ((c ^ (m & 7)) << 4),
                 g_inph + (size_t)plane * APLANE + (size_t)m * 2048 + kk * 64 + c * 8);
        }
    };

    float wv[32], wv2[32];
    loadW(0, wv);
    cpA(0, 0);
    CP_COMMIT();

    #pragma unroll 1
    for (int kk = 0; kk < 16; kk++) {
        const int buf = kk & 1;
        stsB(wv, buf);
        if (kk < 15) loadW(kk + 1, wv2);
        CP_WAIT0();
        __syncthreads();
        if (kk < 15) { cpA(kk + 1, buf ^ 1); CP_COMMIT(); }
        #pragma unroll
        for (int seg = 0; seg < 3; seg++) {
            const uint32_t abase = sb + buf * 16384 + (seg == 2 ? 8192 : 0);
            const uint32_t bbase = sb + 32768 + buf * 16384 + (seg == 1 ? 8192 : 0);
            #pragma unroll
            for (int kk2 = 0; kk2 < 4; kk2++) {
                uint32_t a0[4], a1[4];
                int ck = kk2 * 2 + hi16;
                LDSM4(a0[0], a0[1], a0[2], a0[3],
                      abase + arow0 * 128 + ((ck ^ (arow0 & 7)) << 4));
                LDSM4(a1[0], a1[1], a1[2], a1[3],
                      abase + arow1 * 128 + ((ck ^ (arow1 & 7)) << 4));
                int kloc = kk2 * 16 + (g8 & 1) * 8 + r8;
                #pragma unroll
                for (int bt = 0; bt < 2; bt++) {
                    int nchunk = wn * 4 + bt * 2 + (g8 >> 1);
                    uint32_t q[4];
                    LDSM4T(q[0], q[1], q[2], q[3],
                           bbase + kloc * 128 + ((nchunk ^ (kloc & 7)) << 4));
                    mma16816(dacc[0 + bt * 2 + 0], a0, q[0], q[1]);
                    mma16816(dacc[0 + bt * 2 + 1], a0, q[2], q[3]);
                    mma16816(dacc[4 + bt * 2 + 0], a1, q[0], q[1]);
                    mma16816(dacc[4 + bt * 2 + 1], a1, q[2], q[3]);
                }
            }
        }
        #pragma unroll
        for (int j = 0; j < 32; j++) wv[j] = wv2[j];
        __syncthreads();
    }
    const int g = lane >> 2;
    const int t = lane & 3;
    #pragma unroll
    for (int at = 0; at < 2; at++)
        #pragma unroll
        for (int bt = 0; bt < 2; bt++)
            #pragma unroll
            for (int h = 0; h < 2; h++) {
                const float* dd = dacc[at * 4 + bt * 2 + h];
                int c0 = n0 + wn * 32 + bt * 16 + h * 8 + 2 * t;
                int r0 = wm * 32 + at * 16 + g;
                if (c0 < Vn) {
                    float bb = db[c0];
                    g_logits[(size_t)r0 * Vn + c0] = dd[0] + bb;
                    g_logits[(size_t)(r0 + 8) * Vn + c0] = dd[2] + bb;
                }
                if (c0 + 1 < Vn) {
                    float bb = db[c0 + 1];
                    g_logits[(size_t)r0 * Vn + c0 + 1] = dd[1] + bb;
                    g_logits[(size_t)(r0 + 8) * Vn + c0 + 1] = dd[3] + bb;
                }
            }
}

// ---------------- softmax over V -> probs ----------------
__global__ void softmax_v_kernel(float* __restrict__ probs) {
    int b = blockIdx.x;
    int tid = threadIdx.x;
    __shared__ float red[1024];
    const float* lg = g_logits + (size_t)b * Vn;
    float m = -1e30f;
    for (int j = tid; j < Vn; j += 1024) m = fmaxf(m, lg[j]);
    red[tid] = m; __syncthreads();
    for (int o = 512; o > 0; o >>= 1) { if (tid < o) red[tid] = fmaxf(red[tid], red[tid + o]); __syncthreads(); }
    m = red[0]; __syncthreads();
    float sum = 0.f;
    float* pb = probs + (size_t)b * Vn;
    for (int j = tid; j < Vn; j += 1024) {
        float e = expf(lg[j] - m);
        pb[j] = e;
        sum += e;
    }
    red[tid] = sum; __syncthreads();
    for (int o = 512; o > 0; o >>= 1) { if (tid < o) red[tid] += red[tid + o]; __syncthreads(); }
    float inv = 1.f / red[0];
    for (int j = tid; j < Vn; j += 1024) pb[j] *= inv;
}

// ---------------- launch ----------------
extern "C" void kernel_launch(void* const* d_in, const int* in_sizes, int n_in,
                              void* d_out, int out_size) {
    const float* enc = (const float*)d_in[0];
    const float* dec = (const float*)d_in[1];
    const float* qh  = (const float*)d_in[2];
    const float* W1  = (const float*)d_in[3];
    const float* b1  = (const float*)d_in[4];
    const float* W2  = (const float*)d_in[5];
    const float* b2  = (const float*)d_in[6];
    const float* aV  = (const float*)d_in[7];
    const float* abV = (const float*)d_in[8];
    const float* lW  = (const float*)d_in[9];
    const float* lb  = (const float*)d_in[10];
    const float* dW  = (const float*)d_in[11];
    const float* db  = (const float*)d_in[12];

    float* out   = (float*)d_out;
    float* probs = out;
    float* hs    = out + (size_t)Bn * Vn;
    float* cs    = hs + (size_t)Ln * Bn * Un;
    float* attnw = cs + (size_t)Ln * Bn * Un;

    static const int RES[8] = {0, 0, 1, 1, 1, 1, 1, 0};

    cudaFuncSetAttribute(score_mma_kernel,
                         cudaFuncAttributeMaxDynamicSharedMemorySize, SC_SMEM);

    copy_x_kernel<<<256, 256>>>(dec);
    ench_kernel<<<65536, 256>>>(enc);
    conv_w1_kernel<<<dim3(32, 32), dim3(32, 8)>>>(W1);
    q2_split_kernel<<<dim3(8, 32), 256>>>(qh, W2);
    q2_fin_kernel<<<256, 256>>>(b1, b2);
    score_mma_kernel<<<dim3(Sn / 64, Bn), 256, SC_SMEM>>>(aV, abV);
    softmax_s_kernel<<<Bn, 256>>>(attnw);
    ctx_part_kernel<<<dim3(Bn, 4, 8), 128>>>();
    ctx_fin_kernel<<<256, 256>>>();

    for (int l = 0; l < Ln; l++) {
        lstm_mma_kernel<<<dim3(48, 8), 128>>>(lW + (size_t)l * 2048 * 4096);
        lstm_act_kernel<<<Bn, 1024>>>(lb + (size_t)l * 4096, hs, cs, l, RES[l]);
    }

    dense_mma_kernel<<<VnP / 64, 128>>>(dW, db);
    softmax_v_kernel<<<Bn, 1024>>>(probs);
}